// round 6
// baseline (speedup 1.0000x reference)
#include <cuda_runtime.h>
#include <cuda_bf16.h>
#include <cstdint>
#include <math.h>

#define Bb   2
#define Tt   2048
#define HIDD 2048
#define NH   16
#define KVH  4
#define HD   128
#define Mrows (Bb*Tt)

// ---------------- scratch (device globals: allocation-free) ----------------
__device__ float g_Qf[(size_t)Bb*NH*Tt*HD];
__device__ float g_Kf[(size_t)Bb*KVH*Tt*HD];
__device__ __nv_bfloat16 g_hsh[(size_t)Mrows*HIDD], g_hsl[(size_t)Mrows*HIDD];
__device__ __nv_bfloat16 g_wqh[(size_t)HIDD*NH*HD],  g_wql[(size_t)HIDD*NH*HD];
__device__ __nv_bfloat16 g_wkh[(size_t)HIDD*KVH*HD], g_wkl[(size_t)HIDD*KVH*HD];
__device__ __nv_bfloat16 g_wvh[(size_t)HIDD*KVH*HD], g_wvl[(size_t)HIDD*KVH*HD];
__device__ __nv_bfloat16 g_woh[(size_t)HIDD*HIDD],   g_wol[(size_t)HIDD*HIDD];
__device__ __nv_bfloat16 g_Qh[(size_t)Bb*NH*Tt*HD],  g_Ql[(size_t)Bb*NH*Tt*HD];
__device__ __nv_bfloat16 g_Kh[(size_t)Bb*KVH*Tt*HD], g_Kl[(size_t)Bb*KVH*Tt*HD];
__device__ __nv_bfloat16 g_Vh[(size_t)Bb*KVH*Tt*HD], g_Vl[(size_t)Bb*KVH*Tt*HD];
__device__ __nv_bfloat16 g_cth[(size_t)Mrows*HIDD],  g_ctl[(size_t)Mrows*HIDD];

// ================= helpers =====================
__device__ __forceinline__ uint32_t smem_u32(const void* p) {
    uint32_t a;
    asm("{ .reg .u64 t; cvta.to.shared.u64 t, %1; cvt.u32.u64 %0, t; }" : "=r"(a) : "l"(p));
    return a;
}
__device__ __forceinline__ void ldm_x4(uint32_t& r0, uint32_t& r1, uint32_t& r2,
                                       uint32_t& r3, uint32_t addr) {
    asm volatile("ldmatrix.sync.aligned.m8n8.x4.shared.b16 {%0,%1,%2,%3}, [%4];"
                 : "=r"(r0), "=r"(r1), "=r"(r2), "=r"(r3) : "r"(addr));
}
__device__ __forceinline__ void ldm_x4_trans(uint32_t& r0, uint32_t& r1, uint32_t& r2,
                                             uint32_t& r3, uint32_t addr) {
    asm volatile("ldmatrix.sync.aligned.m8n8.x4.trans.shared.b16 {%0,%1,%2,%3}, [%4];"
                 : "=r"(r0), "=r"(r1), "=r"(r2), "=r"(r3) : "r"(addr));
}
__device__ __forceinline__ void mma16816(float* c, uint32_t a0, uint32_t a1,
                                         uint32_t a2, uint32_t a3,
                                         uint32_t b0, uint32_t b1) {
    asm volatile(
        "mma.sync.aligned.m16n8k16.row.col.f32.bf16.bf16.f32 "
        "{%0,%1,%2,%3}, {%4,%5,%6,%7}, {%8,%9}, {%0,%1,%2,%3};"
        : "+f"(c[0]), "+f"(c[1]), "+f"(c[2]), "+f"(c[3])
        : "r"(a0), "r"(a1), "r"(a2), "r"(a3), "r"(b0), "r"(b1));
}
__device__ __forceinline__ float ex2(float x) {
    float r;
    asm("ex2.approx.f32 %0, %1;" : "=f"(r) : "f"(x));
    return r;
}
__device__ __forceinline__ void cpa16(uint32_t dst, const void* src) {
    asm volatile("cp.async.cg.shared.global [%0], [%1], 16;" :: "r"(dst), "l"(src));
}
#define CPA_COMMIT() asm volatile("cp.async.commit_group;" ::: "memory")
#define CPA_WAIT1()  asm volatile("cp.async.wait_group 1;" ::: "memory")
#define CPA_WAIT0()  asm volatile("cp.async.wait_group 0;" ::: "memory")

__device__ __forceinline__ void split4(float4 v, uint32_t& h0, uint32_t& h1,
                                       uint32_t& l0, uint32_t& l1) {
    __nv_bfloat162 a = __floats2bfloat162_rn(v.x, v.y);
    __nv_bfloat162 b = __floats2bfloat162_rn(v.z, v.w);
    __nv_bfloat162 ra = __floats2bfloat162_rn(v.x - __bfloat162float(a.x),
                                              v.y - __bfloat162float(a.y));
    __nv_bfloat162 rb = __floats2bfloat162_rn(v.z - __bfloat162float(b.x),
                                              v.w - __bfloat162float(b.y));
    h0 = *(uint32_t*)&a; h1 = *(uint32_t*)&b;
    l0 = *(uint32_t*)&ra; l1 = *(uint32_t*)&rb;
}
__device__ __forceinline__ uint32_t pack_hi(float x, float y) {
    __nv_bfloat162 h = __floats2bfloat162_rn(x, y);
    return *(uint32_t*)&h;
}
__device__ __forceinline__ uint32_t pack_lo(float x, float y, uint32_t hbits) {
    __nv_bfloat162 h = *(__nv_bfloat162*)&hbits;
    __nv_bfloat162 l = __floats2bfloat162_rn(x - __bfloat162float(h.x),
                                             y - __bfloat162float(h.y));
    return *(uint32_t*)&l;
}

// ---------------- convert: fp32 -> bf16 hi/lo ----------------
__global__ void cvt_kernel(const float* __restrict__ x, __nv_bfloat16* __restrict__ h,
                           __nv_bfloat16* __restrict__ l, int n4)
{
    int i = blockIdx.x * blockDim.x + threadIdx.x;
    if (i >= n4) return;
    float4 v = *(const float4*)(x + (size_t)i * 4);
    uint32_t h0, h1, l0, l1;
    split4(v, h0, h1, l0, l1);
    *(uint32_t*)((char*)h + (size_t)i * 8)     = h0;
    *(uint32_t*)((char*)h + (size_t)i * 8 + 4) = h1;
    *(uint32_t*)((char*)l + (size_t)i * 8)     = l0;
    *(uint32_t*)((char*)l + (size_t)i * 8 + 4) = l1;
}

// ---------------- RoPE + convert: fp32 [B,H,T,HD] -> bf16 hi/lo ----------------
__global__ void rope_cvt_kernel(const float* __restrict__ X, const float* __restrict__ cs,
                                const float* __restrict__ sn,
                                __nv_bfloat16* __restrict__ Xh, __nv_bfloat16* __restrict__ Xl,
                                int total)
{
    int i = blockIdx.x * blockDim.x + threadIdx.x;
    if (i >= total) return;
    int d = i & 63;
    int rest = i >> 6;
    int t = rest & (Tt - 1);
    const float* row = X + ((size_t)rest << 7);
    float x1 = row[d], x2 = row[d + 64];
    float c1 = cs[(t << 7) + d],      s1 = sn[(t << 7) + d];
    float c2 = cs[(t << 7) + d + 64], s2 = sn[(t << 7) + d + 64];
    float y1 = x1 * c1 - x2 * s1;
    float y2 = x2 * c2 + x1 * s2;
    size_t base = ((size_t)rest << 7) + d;
    __nv_bfloat16 h1 = __float2bfloat16(y1);
    __nv_bfloat16 h2 = __float2bfloat16(y2);
    Xh[base]      = h1;  Xl[base]      = __float2bfloat16(y1 - __bfloat162float(h1));
    Xh[base + 64] = h2;  Xl[base + 64] = __float2bfloat16(y2 - __bfloat162float(h2));
}

// ======== pipelined mma.sync GEMM: C[M,N] = A[M,K] @ B[K,N], hi/lo bf16 =====
// A (hi/lo) [M,K] bf16, B (hi/lo) [K,N] bf16, cp.async 2-stage, BK=32.
// mode 0: fp32 row-major.  mode 1: fp32 head layout.  mode 3: bf16 hi/lo head.
#define SP  40
#define BSP 136
#define G_AH 0
#define G_AL 10240
#define G_BH 20480
#define G_BL 29184
#define G_STG 37888

__device__ __forceinline__ void gemm_issue(
    const __nv_bfloat16* Ah, const __nv_bfloat16* Al,
    const __nv_bfloat16* Bh, const __nv_bfloat16* Bl,
    uint32_t sb, int tid, int m0, int n0, int K, int N, int k0)
{
    #pragma unroll
    for (int r = 0; r < 2; ++r) {
        int e = tid * 2 + r;                 // 0..511
        int row = e >> 2, seg = e & 3;       // A: 128 rows x 4 segs(16B)
        size_t gofs = (size_t)(m0 + row) * K + k0 + seg * 8;
        uint32_t s = (uint32_t)(row * SP + seg * 8) * 2;
        cpa16(sb + G_AH + s, Ah + gofs);
        cpa16(sb + G_AL + s, Al + gofs);
    }
    #pragma unroll
    for (int r = 0; r < 2; ++r) {
        int e = tid * 2 + r;
        int row = e >> 4, seg = e & 15;      // B: 32 rows x 16 segs(16B)
        size_t gofs = (size_t)(k0 + row) * N + n0 + seg * 8;
        uint32_t s = (uint32_t)(row * BSP + seg * 8) * 2;
        cpa16(sb + G_BH + s, Bh + gofs);
        cpa16(sb + G_BL + s, Bl + gofs);
    }
}

__global__ __launch_bounds__(256, 2) void tc_gemm2(
    const __nv_bfloat16* __restrict__ Ah, const __nv_bfloat16* __restrict__ Al,
    const __nv_bfloat16* __restrict__ Bh, const __nv_bfloat16* __restrict__ Bl,
    float* __restrict__ C, __nv_bfloat16* __restrict__ Ch, __nv_bfloat16* __restrict__ Cl,
    int N, int K, int mode, int H)
{
    extern __shared__ char gsm[];
    uint32_t sb = smem_u32(gsm);

    int tid = threadIdx.x;
    int wid = tid >> 5, lane = tid & 31;
    int wm = wid >> 2, wn = wid & 3;
    int m0 = blockIdx.y << 7, n0 = blockIdx.x << 7;
    int r16 = lane & 15, hsel = lane >> 4;

    float acc[4][4][4];
    #pragma unroll
    for (int i = 0; i < 4; ++i)
        #pragma unroll
        for (int j = 0; j < 4; ++j)
            #pragma unroll
            for (int e = 0; e < 4; ++e) acc[i][j][e] = 0.f;

    int chunks = K >> 5;
    gemm_issue(Ah, Al, Bh, Bl, sb,          tid, m0, n0, K, N, 0);
    CPA_COMMIT();
    gemm_issue(Ah, Al, Bh, Bl, sb + G_STG,  tid, m0, n0, K, N, 32);
    CPA_COMMIT();

    for (int i = 0; i < chunks; ++i) {
        uint32_t st = sb + (i & 1) * G_STG;
        if (i == chunks - 1) { CPA_WAIT0(); } else { CPA_WAIT1(); }
        __syncthreads();

        #pragma unroll
        for (int ks = 0; ks < 2; ++ks) {
            uint32_t bh[2][4], bl[2][4];
            #pragma unroll
            for (int j2 = 0; j2 < 2; ++j2) {
                uint32_t boff = (uint32_t)((ks * 16 + r16) * BSP +
                                           (wn << 5) + (j2 << 4) + (hsel << 3)) << 1;
                ldm_x4_trans(bh[j2][0], bh[j2][1], bh[j2][2], bh[j2][3], st + G_BH + boff);
                ldm_x4_trans(bl[j2][0], bl[j2][1], bl[j2][2], bl[j2][3], st + G_BL + boff);
            }
            #pragma unroll
            for (int ii = 0; ii < 4; ++ii) {
                uint32_t aoff = (uint32_t)(((wm << 6) + (ii << 4) + r16) * SP +
                                           ks * 16 + (hsel << 3)) << 1;
                uint32_t ah0, ah1, ah2, ah3, al0, al1, al2, al3;
                ldm_x4(ah0, ah1, ah2, ah3, st + G_AH + aoff);
                ldm_x4(al0, al1, al2, al3, st + G_AL + aoff);
                #pragma unroll
                for (int j2 = 0; j2 < 2; ++j2) {
                    mma16816(acc[ii][2*j2],   ah0, ah1, ah2, ah3, bh[j2][0], bh[j2][1]);
                    mma16816(acc[ii][2*j2+1], ah0, ah1, ah2, ah3, bh[j2][2], bh[j2][3]);
                    mma16816(acc[ii][2*j2],   ah0, ah1, ah2, ah3, bl[j2][0], bl[j2][1]);
                    mma16816(acc[ii][2*j2+1], ah0, ah1, ah2, ah3, bl[j2][2], bl[j2][3]);
                    mma16816(acc[ii][2*j2],   al0, al1, al2, al3, bh[j2][0], bh[j2][1]);
                    mma16816(acc[ii][2*j2+1], al0, al1, al2, al3, bh[j2][2], bh[j2][3]);
                }
            }
        }
        __syncthreads();
        if (i + 2 < chunks) {
            gemm_issue(Ah, Al, Bh, Bl, sb + (i & 1) * G_STG, tid, m0, n0, K, N, (i + 2) << 5);
            CPA_COMMIT();
        }
    }

    // ---- epilogue ----
    int g = lane >> 2, q = lane & 3;
    #pragma unroll
    for (int i = 0; i < 4; ++i) {
        #pragma unroll
        for (int half = 0; half < 2; ++half) {
            int m = m0 + (wm << 6) + (i << 4) + g + (half << 3);
            size_t base;
            if (mode == 0) {
                base = (size_t)m * N + n0;
            } else {
                int b = m >> 11, t = m & (Tt - 1), h = n0 >> 7;
                base = ((size_t)(b * H + h) * Tt + t) << 7;
            }
            #pragma unroll
            for (int j = 0; j < 4; ++j) {
                int nl = (wn << 5) + (j << 3) + (q << 1);
                float vx = acc[i][j][half * 2];
                float vy = acc[i][j][half * 2 + 1];
                if (mode == 3) {
                    uint32_t hp = pack_hi(vx, vy);
                    uint32_t lp = pack_lo(vx, vy, hp);
                    *(uint32_t*)((char*)Ch + (base + nl) * 2) = hp;
                    *(uint32_t*)((char*)Cl + (base + nl) * 2) = lp;
                } else {
                    *(float2*)(C + base + nl) = make_float2(vx, vy);
                }
            }
        }
    }
}

// ========== pipelined flash attention (mma.sync, causal, GQA) ==============
#define FSP 136
#define F_QH 0
#define F_QL 34816
#define F_KV0 69632
#define F_KSTG 69632
#define F_KH 0
#define F_KL 17408
#define F_VH 34816
#define F_VL 52224

__global__ __launch_bounds__(256, 1) void flash_mma2(
    const __nv_bfloat16* __restrict__ Qh_g, const __nv_bfloat16* __restrict__ Ql_g,
    const __nv_bfloat16* __restrict__ Kh_g, const __nv_bfloat16* __restrict__ Kl_g,
    const __nv_bfloat16* __restrict__ Vh_g, const __nv_bfloat16* __restrict__ Vl_g,
    __nv_bfloat16* __restrict__ Ch, __nv_bfloat16* __restrict__ Cl)
{
    extern __shared__ char fsm[];
    uint32_t sb = smem_u32(fsm);

    int tid = threadIdx.x, wid = tid >> 5, lane = tid & 31;
    int g = lane >> 2, qd = lane & 3;
    int r16 = lane & 15, hsel = lane >> 4;
    int qt = blockIdx.x, bh = blockIdx.y;
    int b = bh >> 4, h = bh & 15, kvh = h >> 2;

    size_t qoff = ((size_t)(b * NH + h) * Tt + qt * 128) << 7;
    size_t kvoff = ((size_t)(b * KVH + kvh) * Tt) << 7;

    // ---- prologue: Q tile + KV tile 0 (group 0), KV tile 1 (group 1) ----
    {
        #pragma unroll
        for (int r = 0; r < 8; ++r) {
            int e = tid + r * 256;             // 0..2047
            int row = e >> 4, seg = e & 15;    // 128 rows x 16 segs
            size_t gofs = qoff + ((size_t)row << 7) + seg * 8;
            uint32_t s = (uint32_t)(row * FSP + seg * 8) * 2;
            cpa16(sb + F_QH + s, Qh_g + gofs);
            cpa16(sb + F_QL + s, Ql_g + gofs);
        }
        #pragma unroll
        for (int r = 0; r < 4; ++r) {
            int e = tid + r * 256;             // 0..1023
            int row = e >> 4, seg = e & 15;    // 64 rows x 16 segs
            size_t gofs = kvoff + ((size_t)row << 7) + seg * 8;
            uint32_t s = (uint32_t)(row * FSP + seg * 8) * 2;
            cpa16(sb + F_KV0 + F_KH + s, Kh_g + gofs);
            cpa16(sb + F_KV0 + F_KL + s, Kl_g + gofs);
            cpa16(sb + F_KV0 + F_VH + s, Vh_g + gofs);
            cpa16(sb + F_KV0 + F_VL + s, Vl_g + gofs);
        }
        CPA_COMMIT();
        #pragma unroll
        for (int r = 0; r < 4; ++r) {
            int e = tid + r * 256;
            int row = e >> 4, seg = e & 15;
            size_t gofs = kvoff + ((size_t)(64 + row) << 7) + seg * 8;
            uint32_t s = (uint32_t)(row * FSP + seg * 8) * 2;
            cpa16(sb + F_KV0 + F_KSTG + F_KH + s, Kh_g + gofs);
            cpa16(sb + F_KV0 + F_KSTG + F_KL + s, Kl_g + gofs);
            cpa16(sb + F_KV0 + F_KSTG + F_VH + s, Vh_g + gofs);
            cpa16(sb + F_KV0 + F_KSTG + F_VL + s, Vl_g + gofs);
        }
        CPA_COMMIT();
    }

    float o[16][4];
    #pragma unroll
    for (int i = 0; i < 16; ++i)
        #pragma unroll
        for (int e = 0; e < 4; ++e) o[i][e] = 0.f;
    float m0 = -1e30f, m1 = -1e30f, l0 = 0.f, l1 = 0.f;
    const float alpha = 0.08838834764831845f * 1.4426950408889634f;

    int qbase = qt * 128 + wid * 16;
    int ntiles = 2 * qt + 2;

    for (int jt = 0; jt < ntiles; ++jt) {
        uint32_t st = sb + F_KV0 + (jt & 1) * F_KSTG;
        if (jt == ntiles - 1) { CPA_WAIT0(); } else { CPA_WAIT1(); }
        __syncthreads();

        // ---- S = Q K^T (3-term hi/lo) ----
        float s[8][4];
        #pragma unroll
        for (int t8 = 0; t8 < 8; ++t8)
            #pragma unroll
            for (int e = 0; e < 4; ++e) s[t8][e] = 0.f;

        #pragma unroll
        for (int ks = 0; ks < 8; ++ks) {
            uint32_t aoff = (uint32_t)((wid * 16 + r16) * FSP + ks * 16 + (hsel << 3)) << 1;
            uint32_t ah0, ah1, ah2, ah3, al0, al1, al2, al3;
            ldm_x4(ah0, ah1, ah2, ah3, sb + F_QH + aoff);
            ldm_x4(al0, al1, al2, al3, sb + F_QL + aoff);
            #pragma unroll
            for (int nt = 0; nt < 4; ++nt) {
                uint32_t koff = (uint32_t)((nt * 16 + r16) * FSP + ks * 16 + (hsel << 3)) << 1;
                uint32_t kh0, kh1, kh2, kh3, kl0, kl1, kl2, kl3;
                ldm_x4(kh0, kh1, kh2, kh3, st + F_KH + koff);
                ldm_x4(kl0, kl1, kl2, kl3, st + F_KL + koff);
                mma16816(s[2*nt],   ah0, ah1, ah2, ah3, kh0, kh2);
                mma16816(s[2*nt+1], ah0, ah1, ah2, ah3, kh1, kh3);
                mma16816(s[2*nt],   ah0, ah1, ah2, ah3, kl0, kl2);
                mma16816(s[2*nt+1], ah0, ah1, ah2, ah3, kl1, kl3);
                mma16816(s[2*nt],   al0, al1, al2, al3, kh0, kh2);
                mma16816(s[2*nt+1], al0, al1, al2, al3, kh1, kh3);
            }
        }

        // ---- scale + causal mask ----
        int kvb = jt * 64;
        int qr0 = qbase + g;
        bool needmask = (kvb + 63 > qbase);
        #pragma unroll
        for (int t8 = 0; t8 < 8; ++t8) {
            #pragma unroll
            for (int e = 0; e < 4; ++e) {
                float val = s[t8][e] * alpha;
                if (needmask) {
                    int col = kvb + t8 * 8 + qd * 2 + (e & 1);
                    int row = (e < 2) ? qr0 : qr0 + 8;
                    if (col > row) val = -1e30f;
                }
                s[t8][e] = val;
            }
        }

        // ---- online softmax ----
        float tm0 = -1e30f, tm1 = -1e30f;
        #pragma unroll
        for (int t8 = 0; t8 < 8; ++t8) {
            tm0 = fmaxf(tm0, fmaxf(s[t8][0], s[t8][1]));
            tm1 = fmaxf(tm1, fmaxf(s[t8][2], s[t8][3]));
        }
        tm0 = fmaxf(tm0, __shfl_xor_sync(0xffffffffu, tm0, 1));
        tm0 = fmaxf(tm0, __shfl_xor_sync(0xffffffffu, tm0, 2));
        tm1 = fmaxf(tm1, __shfl_xor_sync(0xffffffffu, tm1, 1));
        tm1 = fmaxf(tm1, __shfl_xor_sync(0xffffffffu, tm1, 2));
        float nm0 = fmaxf(m0, tm0), nm1 = fmaxf(m1, tm1);
        float c0 = ex2(m0 - nm0), c1 = ex2(m1 - nm1);
        m0 = nm0; m1 = nm1;

        float ps0 = 0.f, ps1 = 0.f;
        #pragma unroll
        for (int t8 = 0; t8 < 8; ++t8) {
            s[t8][0] = ex2(s[t8][0] - nm0);
            s[t8][1] = ex2(s[t8][1] - nm0);
            s[t8][2] = ex2(s[t8][2] - nm1);
            s[t8][3] = ex2(s[t8][3] - nm1);
            ps0 += s[t8][0] + s[t8][1];
            ps1 += s[t8][2] + s[t8][3];
        }
        ps0 += __shfl_xor_sync(0xffffffffu, ps0, 1);
        ps0 += __shfl_xor_sync(0xffffffffu, ps0, 2);
        ps1 += __shfl_xor_sync(0xffffffffu, ps1, 1);
        ps1 += __shfl_xor_sync(0xffffffffu, ps1, 2);
        l0 = l0 * c0 + ps0;
        l1 = l1 * c1 + ps1;

        #pragma unroll
        for (int dt = 0; dt < 16; ++dt) {
            o[dt][0] *= c0; o[dt][1] *= c0;
            o[dt][2] *= c1; o[dt][3] *= c1;
        }

        // ---- O += P V (3-term hi/lo) ----
        #pragma unroll
        for (int j = 0; j < 4; ++j) {
            uint32_t ph0 = pack_hi(s[2*j][0],   s[2*j][1]);
            uint32_t ph1 = pack_hi(s[2*j][2],   s[2*j][3]);
            uint32_t ph2 = pack_hi(s[2*j+1][0], s[2*j+1][1]);
            uint32_t ph3 = pack_hi(s[2*j+1][2], s[2*j+1][3]);
            uint32_t pl0 = pack_lo(s[2*j][0],   s[2*j][1],   ph0);
            uint32_t pl1 = pack_lo(s[2*j][2],   s[2*j][3],   ph1);
            uint32_t pl2 = pack_lo(s[2*j+1][0], s[2*j+1][1], ph2);
            uint32_t pl3 = pack_lo(s[2*j+1][2], s[2*j+1][3], ph3);
            #pragma unroll
            for (int dt = 0; dt < 8; ++dt) {
                uint32_t voff = (uint32_t)((j * 16 + r16) * FSP + dt * 16 + (hsel << 3)) << 1;
                uint32_t vh0, vh1, vh2, vh3, vl0, vl1, vl2, vl3;
                ldm_x4_trans(vh0, vh1, vh2, vh3, st + F_VH + voff);
                ldm_x4_trans(vl0, vl1, vl2, vl3, st + F_VL + voff);
                mma16816(o[2*dt],   ph0, ph1, ph2, ph3, vh0, vh1);
                mma16816(o[2*dt+1], ph0, ph1, ph2, ph3, vh2, vh3);
                mma16816(o[2*dt],   pl0, pl1, pl2, pl3, vh0, vh1);
                mma16816(o[2*dt+1], pl0, pl1, pl2, pl3, vh2, vh3);
                mma16816(o[2*dt],   ph0, ph1, ph2, ph3, vl0, vl1);
                mma16816(o[2*dt+1], ph0, ph1, ph2, ph3, vl2, vl3);
            }
        }

        __syncthreads();
        if (jt + 2 < ntiles) {
            uint32_t dst = sb + F_KV0 + (jt & 1) * F_KSTG;
            #pragma unroll
            for (int r = 0; r < 4; ++r) {
                int e = tid + r * 256;
                int row = e >> 4, seg = e & 15;
                size_t gofs = kvoff + ((size_t)((jt + 2) * 64 + row) << 7) + seg * 8;
                uint32_t s2 = (uint32_t)(row * FSP + seg * 8) * 2;
                cpa16(dst + F_KH + s2, Kh_g + gofs);
                cpa16(dst + F_KL + s2, Kl_g + gofs);
                cpa16(dst + F_VH + s2, Vh_g + gofs);
                cpa16(dst + F_VL + s2, Vl_g + gofs);
            }
            CPA_COMMIT();
        }
    }

    // ---- finalize: write ctx as bf16 hi/lo ----
    float li0 = 1.f / l0, li1 = 1.f / l1;
    int t0 = qbase + g;
    size_t d0 = (size_t)(b * Tt + t0) * HIDD + h * HD;
    size_t d1 = (size_t)(b * Tt + t0 + 8) * HIDD + h * HD;
    #pragma unroll
    for (int dt = 0; dt < 16; ++dt) {
        int col = dt * 8 + qd * 2;
        float x0 = o[dt][0] * li0, y0 = o[dt][1] * li0;
        float x1 = o[dt][2] * li1, y1 = o[dt][3] * li1;
        uint32_t hp0 = pack_hi(x0, y0), lp0 = pack_lo(x0, y0, hp0);
        uint32_t hp1 = pack_hi(x1, y1), lp1 = pack_lo(x1, y1, hp1);
        *(uint32_t*)((char*)Ch + (d0 + col) * 2) = hp0;
        *(uint32_t*)((char*)Cl + (d0 + col) * 2) = lp0;
        *(uint32_t*)((char*)Ch + (d1 + col) * 2) = hp1;
        *(uint32_t*)((char*)Cl + (d1 + col) * 2) = lp1;
    }
}

// ---------------- launch ----------------
extern "C" void kernel_launch(void* const* d_in, const int* in_sizes, int n_in,
                              void* d_out, int out_size)
{
    const float* hs   = (const float*)d_in[0];
    const float* cosp = (const float*)d_in[2];
    const float* sinp = (const float*)d_in[3];
    const float* Wq   = (const float*)d_in[4];
    const float* Wk   = (const float*)d_in[5];
    const float* Wv   = (const float*)d_in[6];
    const float* Wo   = (const float*)d_in[7];
    float* out = (float*)d_out;

    float *pQf, *pKf;
    __nv_bfloat16 *hsh, *hsl, *wqh, *wql, *wkh, *wkl, *wvh, *wvl, *woh, *wol;
    __nv_bfloat16 *Qh, *Ql, *Kh, *Kl, *Vh, *Vl, *cth, *ctl;
    cudaGetSymbolAddress((void**)&pQf, g_Qf);
    cudaGetSymbolAddress((void**)&pKf, g_Kf);
    cudaGetSymbolAddress((void**)&hsh, g_hsh); cudaGetSymbolAddress((void**)&hsl, g_hsl);
    cudaGetSymbolAddress((void**)&wqh, g_wqh); cudaGetSymbolAddress((void**)&wql, g_wql);
    cudaGetSymbolAddress((void**)&wkh, g_wkh); cudaGetSymbolAddress((void**)&wkl, g_wkl);
    cudaGetSymbolAddress((void**)&wvh, g_wvh); cudaGetSymbolAddress((void**)&wvl, g_wvl);
    cudaGetSymbolAddress((void**)&woh, g_woh); cudaGetSymbolAddress((void**)&wol, g_wol);
    cudaGetSymbolAddress((void**)&Qh, g_Qh); cudaGetSymbolAddress((void**)&Ql, g_Ql);
    cudaGetSymbolAddress((void**)&Kh, g_Kh); cudaGetSymbolAddress((void**)&Kl, g_Kl);
    cudaGetSymbolAddress((void**)&Vh, g_Vh); cudaGetSymbolAddress((void**)&Vl, g_Vl);
    cudaGetSymbolAddress((void**)&cth, g_cth); cudaGetSymbolAddress((void**)&ctl, g_ctl);

    // ---- pre-convert inputs to bf16 hi/lo ----
    cvt_kernel<<<(Mrows*HIDD/4 + 255)/256, 256>>>(hs, hsh, hsl, Mrows*HIDD/4);
    cvt_kernel<<<(HIDD*NH*HD/4 + 255)/256, 256>>>(Wq, wqh, wql, HIDD*NH*HD/4);
    cvt_kernel<<<(HIDD*KVH*HD/4 + 255)/256, 256>>>(Wk, wkh, wkl, HIDD*KVH*HD/4);
    cvt_kernel<<<(HIDD*KVH*HD/4 + 255)/256, 256>>>(Wv, wvh, wvl, HIDD*KVH*HD/4);
    cvt_kernel<<<(HIDD*HIDD/4 + 255)/256, 256>>>(Wo, woh, wol, HIDD*HIDD/4);

    size_t gsh = 2 * G_STG;  // 75776
    cudaFuncSetAttribute(tc_gemm2, cudaFuncAttributeMaxDynamicSharedMemorySize, (int)gsh);

    // QKV projections
    tc_gemm2<<<dim3(16, 32), 256, gsh>>>(hsh, hsl, wqh, wql, pQf, nullptr, nullptr, NH*HD,  HIDD, 1, NH);
    tc_gemm2<<<dim3(4,  32), 256, gsh>>>(hsh, hsl, wkh, wkl, pKf, nullptr, nullptr, KVH*HD, HIDD, 1, KVH);
    tc_gemm2<<<dim3(4,  32), 256, gsh>>>(hsh, hsl, wvh, wvl, nullptr, Vh, Vl,       KVH*HD, HIDD, 3, KVH);

    // RoPE + convert Q, K to bf16 hi/lo
    int totQ = Bb * NH  * Tt * 64;
    int totK = Bb * KVH * Tt * 64;
    rope_cvt_kernel<<<totQ / 256, 256>>>(pQf, cosp, sinp, Qh, Ql, totQ);
    rope_cvt_kernel<<<totK / 256, 256>>>(pKf, cosp, sinp, Kh, Kl, totK);

    // Flash attention (pipelined)
    size_t fsh = (size_t)F_KV0 + 2 * F_KSTG;  // 208896
    cudaFuncSetAttribute(flash_mma2, cudaFuncAttributeMaxDynamicSharedMemorySize, (int)fsh);
    flash_mma2<<<dim3(Tt/128, Bb*NH), 256, fsh>>>(Qh, Ql, Kh, Kl, Vh, Vl, cth, ctl);

    // Output projection
    tc_gemm2<<<dim3(16, 32), 256, gsh>>>(cth, ctl, woh, wol, out, nullptr, nullptr, HIDD, HIDD, 0, 0);
}

// round 8
// speedup vs baseline: 1.4246x; 1.4246x over previous
#include <cuda_runtime.h>
#include <cuda_bf16.h>
#include <cstdint>
#include <math.h>

#define Bb   2
#define Tt   2048
#define HIDD 2048
#define NH   16
#define KVH  4
#define HD   128
#define Mrows (Bb*Tt)

// ---------------- scratch (device globals: allocation-free) ----------------
__device__ float g_Q[(size_t)Bb*NH*Tt*HD];    // [B, NH, T, HD]
__device__ float g_K[(size_t)Bb*KVH*Tt*HD];   // [B, KVH, T, HD]
__device__ float g_V[(size_t)Bb*KVH*Tt*HD];   // [B, KVH, T, HD]
__device__ float g_ctx[(size_t)Bb*Tt*HIDD];   // [B*T, HID]

// ================= mma.sync helpers (compute_103-safe) =====================
__device__ __forceinline__ uint32_t smem_u32(const void* p) {
    uint32_t a;
    asm("{ .reg .u64 t; cvta.to.shared.u64 t, %1; cvt.u32.u64 %0, t; }" : "=r"(a) : "l"(p));
    return a;
}
__device__ __forceinline__ void ldm_x4(uint32_t& r0, uint32_t& r1, uint32_t& r2,
                                       uint32_t& r3, uint32_t addr) {
    asm volatile("ldmatrix.sync.aligned.m8n8.x4.shared.b16 {%0,%1,%2,%3}, [%4];"
                 : "=r"(r0), "=r"(r1), "=r"(r2), "=r"(r3) : "r"(addr));
}
__device__ __forceinline__ void ldm_x4_trans(uint32_t& r0, uint32_t& r1, uint32_t& r2,
                                             uint32_t& r3, uint32_t addr) {
    asm volatile("ldmatrix.sync.aligned.m8n8.x4.trans.shared.b16 {%0,%1,%2,%3}, [%4];"
                 : "=r"(r0), "=r"(r1), "=r"(r2), "=r"(r3) : "r"(addr));
}
__device__ __forceinline__ void mma16816(float* c, uint32_t a0, uint32_t a1,
                                         uint32_t a2, uint32_t a3,
                                         uint32_t b0, uint32_t b1) {
    asm volatile(
        "mma.sync.aligned.m16n8k16.row.col.f32.bf16.bf16.f32 "
        "{%0,%1,%2,%3}, {%4,%5,%6,%7}, {%8,%9}, {%0,%1,%2,%3};"
        : "+f"(c[0]), "+f"(c[1]), "+f"(c[2]), "+f"(c[3])
        : "r"(a0), "r"(a1), "r"(a2), "r"(a3), "r"(b0), "r"(b1));
}
__device__ __forceinline__ float ex2(float x) {
    float r;
    asm("ex2.approx.f32 %0, %1;" : "=f"(r) : "f"(x));
    return r;
}

__device__ __forceinline__ void split4(float4 v, uint32_t& h0, uint32_t& h1,
                                       uint32_t& l0, uint32_t& l1) {
    __nv_bfloat162 a = __floats2bfloat162_rn(v.x, v.y);
    __nv_bfloat162 b = __floats2bfloat162_rn(v.z, v.w);
    __nv_bfloat162 ra = __floats2bfloat162_rn(v.x - __bfloat162float(a.x),
                                              v.y - __bfloat162float(a.y));
    __nv_bfloat162 rb = __floats2bfloat162_rn(v.z - __bfloat162float(b.x),
                                              v.w - __bfloat162float(b.y));
    h0 = *(uint32_t*)&a; h1 = *(uint32_t*)&b;
    l0 = *(uint32_t*)&ra; l1 = *(uint32_t*)&rb;
}
__device__ __forceinline__ uint32_t pack_hi(float x, float y) {
    __nv_bfloat162 h = __floats2bfloat162_rn(x, y);
    return *(uint32_t*)&h;
}
__device__ __forceinline__ uint32_t pack_lo(float x, float y, uint32_t hbits) {
    __nv_bfloat162 h = *(__nv_bfloat162*)&hbits;
    __nv_bfloat162 l = __floats2bfloat162_rn(x - __bfloat162float(h.x),
                                             y - __bfloat162float(h.y));
    return *(uint32_t*)&l;
}

// ======== mma.sync GEMM: C[M,N] = A[M,K] @ W[K,N], bf16 hi/lo split ========
#define SP  40
#define BSP 136

__global__ __launch_bounds__(256, 2) void tc_gemm_kernel(
    const float* __restrict__ A, const float* __restrict__ W,
    float* __restrict__ C, int N, int K, int mode, int H)
{
    __shared__ __align__(16) uint16_t sAh[128 * SP];
    __shared__ __align__(16) uint16_t sAl[128 * SP];
    __shared__ __align__(16) uint16_t sBh[32 * BSP];
    __shared__ __align__(16) uint16_t sBl[32 * BSP];

    const uint32_t uAh = smem_u32(sAh), uAl = smem_u32(sAl);
    const uint32_t uBh = smem_u32(sBh), uBl = smem_u32(sBl);

    int tid = threadIdx.x;
    int wid = tid >> 5, lane = tid & 31;
    int wm = wid >> 2, wn = wid & 3;
    int m0 = blockIdx.y << 7, n0 = blockIdx.x << 7;

    int arow = tid >> 1;
    int acb  = (tid & 1) << 4;
    int bk0  = tid >> 5;
    int bn4  = (tid & 31) << 2;

    const float* apg = A + (size_t)(m0 + arow) * K + acb;
    const float* bpg = W + (size_t)bk0 * N + n0 + bn4;

    float acc[4][4][4];
    #pragma unroll
    for (int i = 0; i < 4; ++i)
        #pragma unroll
        for (int j = 0; j < 4; ++j)
            #pragma unroll
            for (int e = 0; e < 4; ++e) acc[i][j][e] = 0.f;

    for (int k0 = 0; k0 < K; k0 += 32) {
        #pragma unroll
        for (int c = 0; c < 4; ++c) {
            float4 v = *(const float4*)(apg + k0 + (c << 2));
            uint32_t h0, h1, l0, l1;
            split4(v, h0, h1, l0, l1);
            uint32_t off = (uint32_t)(arow * SP + acb + (c << 2)) << 1;
            *(uint32_t*)((char*)sAh + off)     = h0;
            *(uint32_t*)((char*)sAh + off + 4) = h1;
            *(uint32_t*)((char*)sAl + off)     = l0;
            *(uint32_t*)((char*)sAl + off + 4) = l1;
        }
        #pragma unroll
        for (int it = 0; it < 4; ++it) {
            float4 v = *(const float4*)(bpg + (size_t)(k0 + (it << 3)) * N);
            uint32_t h0, h1, l0, l1;
            split4(v, h0, h1, l0, l1);
            uint32_t off = (uint32_t)((bk0 + (it << 3)) * BSP + bn4) << 1;
            *(uint32_t*)((char*)sBh + off)     = h0;
            *(uint32_t*)((char*)sBh + off + 4) = h1;
            *(uint32_t*)((char*)sBl + off)     = l0;
            *(uint32_t*)((char*)sBl + off + 4) = l1;
        }
        __syncthreads();

        int r16 = lane & 15, hsel = lane >> 4;
        #pragma unroll
        for (int ks = 0; ks < 2; ++ks) {
            uint32_t bh[2][4], bl[2][4];
            #pragma unroll
            for (int j2 = 0; j2 < 2; ++j2) {
                uint32_t boff = (uint32_t)((ks * 16 + r16) * BSP +
                                           (wn << 5) + (j2 << 4) + (hsel << 3)) << 1;
                ldm_x4_trans(bh[j2][0], bh[j2][1], bh[j2][2], bh[j2][3], uBh + boff);
                ldm_x4_trans(bl[j2][0], bl[j2][1], bl[j2][2], bl[j2][3], uBl + boff);
            }
            #pragma unroll
            for (int i = 0; i < 4; ++i) {
                uint32_t aoff = (uint32_t)(((wm << 6) + (i << 4) + r16) * SP +
                                           ks * 16 + (hsel << 3)) << 1;
                uint32_t ah0, ah1, ah2, ah3, al0, al1, al2, al3;
                ldm_x4(ah0, ah1, ah2, ah3, uAh + aoff);
                ldm_x4(al0, al1, al2, al3, uAl + aoff);
                #pragma unroll
                for (int j2 = 0; j2 < 2; ++j2) {
                    mma16816(acc[i][2*j2],   ah0, ah1, ah2, ah3, bh[j2][0], bh[j2][1]);
                    mma16816(acc[i][2*j2+1], ah0, ah1, ah2, ah3, bh[j2][2], bh[j2][3]);
                    mma16816(acc[i][2*j2],   ah0, ah1, ah2, ah3, bl[j2][0], bl[j2][1]);
                    mma16816(acc[i][2*j2+1], ah0, ah1, ah2, ah3, bl[j2][2], bl[j2][3]);
                    mma16816(acc[i][2*j2],   al0, al1, al2, al3, bh[j2][0], bh[j2][1]);
                    mma16816(acc[i][2*j2+1], al0, al1, al2, al3, bh[j2][2], bh[j2][3]);
                }
            }
        }
        __syncthreads();
    }

    int g = lane >> 2, q = lane & 3;
    #pragma unroll
    for (int i = 0; i < 4; ++i) {
        #pragma unroll
        for (int half = 0; half < 2; ++half) {
            int m = m0 + (wm << 6) + (i << 4) + g + (half << 3);
            float* dst;
            if (mode == 0) {
                dst = C + (size_t)m * N + n0;
            } else {
                int b = m >> 11, t = m & (Tt - 1), h = n0 >> 7;
                dst = C + (((size_t)(b * H + h) * Tt + t) << 7);
            }
            #pragma unroll
            for (int j = 0; j < 4; ++j) {
                int nl = (wn << 5) + (j << 3) + (q << 1);
                float2 v;
                v.x = acc[i][j][half * 2];
                v.y = acc[i][j][half * 2 + 1];
                *(float2*)(dst + nl) = v;
            }
        }
    }
}

// ---------------- RoPE (in-place on [B,H,T,HD]) ----------------
__global__ void rope_kernel(float* __restrict__ X, const float* __restrict__ cs,
                            const float* __restrict__ sn, int total)
{
    int i = blockIdx.x * blockDim.x + threadIdx.x;
    if (i >= total) return;
    int d = i & 63;
    int rest = i >> 6;
    int t = rest & (Tt - 1);
    float* row = X + ((size_t)rest << 7);
    float x1 = row[d], x2 = row[d + 64];
    float c1 = cs[(t << 7) + d],      s1 = sn[(t << 7) + d];
    float c2 = cs[(t << 7) + d + 64], s2 = sn[(t << 7) + d + 64];
    row[d]      = x1 * c1 - x2 * s1;
    row[d + 64] = x2 * c2 + x1 * s2;
}

// ========== Flash attention on mma.sync (causal, GQA, 3-term hi/lo) ========
// CTA: 256 threads (8 warps), Q tile 128 rows (16 per warp), KV tile 64.
// K/V global loads for tile jt+1 are preloaded into registers during tile jt's
// compute (software pipeline; hides DRAM latency at 1 CTA/SM occupancy).
#define FSP 136   // bf16 row stride (272B: 16B-aligned, ldmatrix conflict-free)

__global__ __launch_bounds__(256, 1) void flash_mma_kernel(
    const float* __restrict__ Q, const float* __restrict__ K,
    const float* __restrict__ V, float* __restrict__ ctx)
{
    extern __shared__ char fsm[];
    uint16_t* Qh = (uint16_t*)fsm;
    uint16_t* Ql = Qh + 128 * FSP;
    uint16_t* Kh = Ql + 128 * FSP;
    uint16_t* Kl = Kh + 64 * FSP;
    uint16_t* Vh = Kl + 64 * FSP;
    uint16_t* Vl = Vh + 64 * FSP;
    const uint32_t uQh = smem_u32(Qh), uQl = smem_u32(Ql);
    const uint32_t uKh = smem_u32(Kh), uKl = smem_u32(Kl);
    const uint32_t uVh = smem_u32(Vh), uVl = smem_u32(Vl);

    int tid = threadIdx.x, wid = tid >> 5, lane = tid & 31;
    int g = lane >> 2, qd = lane & 3;
    int r16 = lane & 15, hsel = lane >> 4;
    int qt = gridDim.x - 1 - blockIdx.x;        // heavy tiles scheduled first
    int bh = blockIdx.y;
    int b = bh >> 4, h = bh & 15, kvh = h >> 2;

    const float* Qp = Q + (((size_t)(b * NH + h) * Tt + qt * 128) << 7);
    const float* Kp = K + (((size_t)(b * KVH + kvh) * Tt) << 7);
    const float* Vp = V + (((size_t)(b * KVH + kvh) * Tt) << 7);

    // ---- stage Q tile (128x128 fp32 -> bf16 hi/lo) ----
    {
        int row = tid >> 1, cb = (tid & 1) << 6;
        const float* qp = Qp + ((size_t)row << 7) + cb;
        #pragma unroll
        for (int i = 0; i < 16; ++i) {
            float4 v = *(const float4*)(qp + (i << 2));
            uint32_t h0, h1, l0, l1;
            split4(v, h0, h1, l0, l1);
            uint32_t off = (uint32_t)(row * FSP + cb + (i << 2)) << 1;
            *(uint32_t*)((char*)Qh + off)     = h0;
            *(uint32_t*)((char*)Qh + off + 4) = h1;
            *(uint32_t*)((char*)Ql + off)     = l0;
            *(uint32_t*)((char*)Ql + off + 4) = l1;
        }
    }

    float o[16][4];
    #pragma unroll
    for (int i = 0; i < 16; ++i)
        #pragma unroll
        for (int e = 0; e < 4; ++e) o[i][e] = 0.f;
    float m0 = -1e30f, m1 = -1e30f, l0 = 0.f, l1 = 0.f;
    const float alpha = 0.08838834764831845f * 1.4426950408889634f; // /sqrt(HD)*log2e

    int qbase = qt * 128 + wid * 16;
    int ntiles = 2 * qt + 2;

    // per-thread staging mapping: one KV row, 32 cols
    int srow = tid >> 2, scb = (tid & 3) << 5;

    // ---- preload KV tile 0 into registers ----
    float4 kr[8], vr[8];
    {
        const float* kp = Kp + ((size_t)srow << 7) + scb;
        const float* vp = Vp + ((size_t)srow << 7) + scb;
        #pragma unroll
        for (int i = 0; i < 8; ++i) {
            kr[i] = *(const float4*)(kp + (i << 2));
            vr[i] = *(const float4*)(vp + (i << 2));
        }
    }

    for (int jt = 0; jt < ntiles; ++jt) {
        __syncthreads();   // previous iteration's smem readers done
        // ---- store+convert preloaded K,V tile ----
        #pragma unroll
        for (int i = 0; i < 8; ++i) {
            uint32_t off = (uint32_t)(srow * FSP + scb + (i << 2)) << 1;
            uint32_t h0, h1, lo0, lo1;
            split4(kr[i], h0, h1, lo0, lo1);
            *(uint32_t*)((char*)Kh + off)     = h0;
            *(uint32_t*)((char*)Kh + off + 4) = h1;
            *(uint32_t*)((char*)Kl + off)     = lo0;
            *(uint32_t*)((char*)Kl + off + 4) = lo1;
            split4(vr[i], h0, h1, lo0, lo1);
            *(uint32_t*)((char*)Vh + off)     = h0;
            *(uint32_t*)((char*)Vh + off + 4) = h1;
            *(uint32_t*)((char*)Vl + off)     = lo0;
            *(uint32_t*)((char*)Vl + off + 4) = lo1;
        }
        __syncthreads();   // staging visible

        // ---- issue next tile's global loads (hidden by compute below) ----
        if (jt + 1 < ntiles) {
            const float* kp = Kp + ((size_t)((jt + 1) * 64 + srow) << 7) + scb;
            const float* vp = Vp + ((size_t)((jt + 1) * 64 + srow) << 7) + scb;
            #pragma unroll
            for (int i = 0; i < 8; ++i) {
                kr[i] = *(const float4*)(kp + (i << 2));
                vr[i] = *(const float4*)(vp + (i << 2));
            }
        }

        // ---- S = Q K^T (3-term hi/lo), s[8][4] frags over kv64 ----
        float s[8][4];
        #pragma unroll
        for (int t8 = 0; t8 < 8; ++t8)
            #pragma unroll
            for (int e = 0; e < 4; ++e) s[t8][e] = 0.f;

        #pragma unroll
        for (int ks = 0; ks < 8; ++ks) {
            uint32_t aoff = (uint32_t)((wid * 16 + r16) * FSP + ks * 16 + (hsel << 3)) << 1;
            uint32_t ah0, ah1, ah2, ah3, al0, al1, al2, al3;
            ldm_x4(ah0, ah1, ah2, ah3, uQh + aoff);
            ldm_x4(al0, al1, al2, al3, uQl + aoff);
            #pragma unroll
            for (int nt = 0; nt < 4; ++nt) {
                uint32_t koff = (uint32_t)((nt * 16 + r16) * FSP + ks * 16 + (hsel << 3)) << 1;
                uint32_t kh0, kh1, kh2, kh3, kl0, kl1, kl2, kl3;
                ldm_x4(kh0, kh1, kh2, kh3, uKh + koff);
                ldm_x4(kl0, kl1, kl2, kl3, uKl + koff);
                mma16816(s[2*nt],   ah0, ah1, ah2, ah3, kh0, kh2);
                mma16816(s[2*nt+1], ah0, ah1, ah2, ah3, kh1, kh3);
                mma16816(s[2*nt],   ah0, ah1, ah2, ah3, kl0, kl2);
                mma16816(s[2*nt+1], ah0, ah1, ah2, ah3, kl1, kl3);
                mma16816(s[2*nt],   al0, al1, al2, al3, kh0, kh2);
                mma16816(s[2*nt+1], al0, al1, al2, al3, kh1, kh3);
            }
        }

        // ---- scale + causal mask ----
        int kvb = jt * 64;
        int qr0 = qbase + g;
        bool needmask = (kvb + 63 > qbase);
        #pragma unroll
        for (int t8 = 0; t8 < 8; ++t8) {
            #pragma unroll
            for (int e = 0; e < 4; ++e) {
                float val = s[t8][e] * alpha;
                if (needmask) {
                    int col = kvb + t8 * 8 + qd * 2 + (e & 1);
                    int row = (e < 2) ? qr0 : qr0 + 8;
                    if (col > row) val = -1e30f;
                }
                s[t8][e] = val;
            }
        }

        // ---- online softmax (quad reductions) ----
        float tm0 = -1e30f, tm1 = -1e30f;
        #pragma unroll
        for (int t8 = 0; t8 < 8; ++t8) {
            tm0 = fmaxf(tm0, fmaxf(s[t8][0], s[t8][1]));
            tm1 = fmaxf(tm1, fmaxf(s[t8][2], s[t8][3]));
        }
        tm0 = fmaxf(tm0, __shfl_xor_sync(0xffffffffu, tm0, 1));
        tm0 = fmaxf(tm0, __shfl_xor_sync(0xffffffffu, tm0, 2));
        tm1 = fmaxf(tm1, __shfl_xor_sync(0xffffffffu, tm1, 1));
        tm1 = fmaxf(tm1, __shfl_xor_sync(0xffffffffu, tm1, 2));
        float nm0 = fmaxf(m0, tm0), nm1 = fmaxf(m1, tm1);
        float c0 = ex2(m0 - nm0), c1 = ex2(m1 - nm1);
        m0 = nm0; m1 = nm1;

        float ps0 = 0.f, ps1 = 0.f;
        #pragma unroll
        for (int t8 = 0; t8 < 8; ++t8) {
            s[t8][0] = ex2(s[t8][0] - nm0);
            s[t8][1] = ex2(s[t8][1] - nm0);
            s[t8][2] = ex2(s[t8][2] - nm1);
            s[t8][3] = ex2(s[t8][3] - nm1);
            ps0 += s[t8][0] + s[t8][1];
            ps1 += s[t8][2] + s[t8][3];
        }
        ps0 += __shfl_xor_sync(0xffffffffu, ps0, 1);
        ps0 += __shfl_xor_sync(0xffffffffu, ps0, 2);
        ps1 += __shfl_xor_sync(0xffffffffu, ps1, 1);
        ps1 += __shfl_xor_sync(0xffffffffu, ps1, 2);
        l0 = l0 * c0 + ps0;
        l1 = l1 * c1 + ps1;

        #pragma unroll
        for (int dt = 0; dt < 16; ++dt) {
            o[dt][0] *= c0; o[dt][1] *= c0;
            o[dt][2] *= c1; o[dt][3] *= c1;
        }

        // ---- O += P V (3-term hi/lo) ----
        #pragma unroll
        for (int j = 0; j < 4; ++j) {
            uint32_t ph0 = pack_hi(s[2*j][0],   s[2*j][1]);
            uint32_t ph1 = pack_hi(s[2*j][2],   s[2*j][3]);
            uint32_t ph2 = pack_hi(s[2*j+1][0], s[2*j+1][1]);
            uint32_t ph3 = pack_hi(s[2*j+1][2], s[2*j+1][3]);
            uint32_t pl0 = pack_lo(s[2*j][0],   s[2*j][1],   ph0);
            uint32_t pl1 = pack_lo(s[2*j][2],   s[2*j][3],   ph1);
            uint32_t pl2 = pack_lo(s[2*j+1][0], s[2*j+1][1], ph2);
            uint32_t pl3 = pack_lo(s[2*j+1][2], s[2*j+1][3], ph3);
            #pragma unroll
            for (int dt = 0; dt < 8; ++dt) {
                uint32_t voff = (uint32_t)((j * 16 + r16) * FSP + dt * 16 + (hsel << 3)) << 1;
                uint32_t vh0, vh1, vh2, vh3, vl0, vl1, vl2, vl3;
                ldm_x4_trans(vh0, vh1, vh2, vh3, uVh + voff);
                ldm_x4_trans(vl0, vl1, vl2, vl3, uVl + voff);
                mma16816(o[2*dt],   ph0, ph1, ph2, ph3, vh0, vh1);
                mma16816(o[2*dt+1], ph0, ph1, ph2, ph3, vh2, vh3);
                mma16816(o[2*dt],   pl0, pl1, pl2, pl3, vh0, vh1);
                mma16816(o[2*dt+1], pl0, pl1, pl2, pl3, vh2, vh3);
                mma16816(o[2*dt],   ph0, ph1, ph2, ph3, vl0, vl1);
                mma16816(o[2*dt+1], ph0, ph1, ph2, ph3, vl2, vl3);
            }
        }
    }

    // ---- finalize ----
    float li0 = 1.f / l0, li1 = 1.f / l1;
    int t0 = qbase + g;
    float* dst0 = ctx + (size_t)(b * Tt + t0) * HIDD + h * HD;
    float* dst1 = ctx + (size_t)(b * Tt + t0 + 8) * HIDD + h * HD;
    #pragma unroll
    for (int dt = 0; dt < 16; ++dt) {
        int col = dt * 8 + qd * 2;
        float2 w0 = make_float2(o[dt][0] * li0, o[dt][1] * li0);
        float2 w1 = make_float2(o[dt][2] * li1, o[dt][3] * li1);
        *(float2*)(dst0 + col) = w0;
        *(float2*)(dst1 + col) = w1;
    }
}

// ---------------- launch ----------------
extern "C" void kernel_launch(void* const* d_in, const int* in_sizes, int n_in,
                              void* d_out, int out_size)
{
    const float* hs   = (const float*)d_in[0];
    const float* cosp = (const float*)d_in[2];
    const float* sinp = (const float*)d_in[3];
    const float* Wq   = (const float*)d_in[4];
    const float* Wk   = (const float*)d_in[5];
    const float* Wv   = (const float*)d_in[6];
    const float* Wo   = (const float*)d_in[7];
    float* out = (float*)d_out;

    float *pQ, *pK, *pV, *pC;
    cudaGetSymbolAddress((void**)&pQ, g_Q);
    cudaGetSymbolAddress((void**)&pK, g_K);
    cudaGetSymbolAddress((void**)&pV, g_V);
    cudaGetSymbolAddress((void**)&pC, g_ctx);

    // QKV projections on mma.sync bf16 hi/lo
    tc_gemm_kernel<<<dim3(16, 32), 256>>>(hs, Wq, pQ, NH*HD,  HIDD, 1, NH);
    tc_gemm_kernel<<<dim3(4,  32), 256>>>(hs, Wk, pK, KVH*HD, HIDD, 1, KVH);
    tc_gemm_kernel<<<dim3(4,  32), 256>>>(hs, Wv, pV, KVH*HD, HIDD, 1, KVH);

    // RoPE on Q and K
    int totQ = Bb * NH  * Tt * 64;
    int totK = Bb * KVH * Tt * 64;
    rope_kernel<<<totQ / 256, 256>>>(pQ, cosp, sinp, totQ);
    rope_kernel<<<totK / 256, 256>>>(pK, cosp, sinp, totK);

    // Flash attention on mma.sync (register-preloaded KV pipeline)
    size_t fsh = (size_t)(2 * 128 * FSP + 4 * 64 * FSP) * sizeof(uint16_t); // 139264
    cudaFuncSetAttribute(flash_mma_kernel, cudaFuncAttributeMaxDynamicSharedMemorySize, (int)fsh);
    flash_mma_kernel<<<dim3(Tt/128, Bb*NH), 256, fsh>>>(pQ, pK, pV, pC);

    // Output projection -> d_out
    tc_gemm_kernel<<<dim3(16, 32), 256>>>(pC, Wo, out, HIDD, HIDD, 0, 0);
}

// round 10
// speedup vs baseline: 1.6563x; 1.1626x over previous
#include <cuda_runtime.h>
#include <cuda_bf16.h>
#include <cuda_fp16.h>
#include <cstdint>
#include <math.h>

#define Bb   2
#define Tt   2048
#define HIDD 2048
#define NH   16
#define KVH  4
#define HD   128
#define Mrows (Bb*Tt)

// ---------------- scratch (device globals: allocation-free) ----------------
__device__ float g_Q[(size_t)Bb*NH*Tt*HD];    // [B, NH, T, HD]
__device__ float g_K[(size_t)Bb*KVH*Tt*HD];   // [B, KVH, T, HD]
__device__ float g_V[(size_t)Bb*KVH*Tt*HD];   // [B, KVH, T, HD]
__device__ float g_ctx[(size_t)Bb*Tt*HIDD];   // [B*T, HID]

// ================= mma.sync helpers (compute_103-safe) =====================
__device__ __forceinline__ uint32_t smem_u32(const void* p) {
    uint32_t a;
    asm("{ .reg .u64 t; cvta.to.shared.u64 t, %1; cvt.u32.u64 %0, t; }" : "=r"(a) : "l"(p));
    return a;
}
__device__ __forceinline__ void ldm_x4(uint32_t& r0, uint32_t& r1, uint32_t& r2,
                                       uint32_t& r3, uint32_t addr) {
    asm volatile("ldmatrix.sync.aligned.m8n8.x4.shared.b16 {%0,%1,%2,%3}, [%4];"
                 : "=r"(r0), "=r"(r1), "=r"(r2), "=r"(r3) : "r"(addr));
}
__device__ __forceinline__ void ldm_x4_trans(uint32_t& r0, uint32_t& r1, uint32_t& r2,
                                             uint32_t& r3, uint32_t addr) {
    asm volatile("ldmatrix.sync.aligned.m8n8.x4.trans.shared.b16 {%0,%1,%2,%3}, [%4];"
                 : "=r"(r0), "=r"(r1), "=r"(r2), "=r"(r3) : "r"(addr));
}
// bf16 mma (flash)
__device__ __forceinline__ void mma16816(float* c, uint32_t a0, uint32_t a1,
                                         uint32_t a2, uint32_t a3,
                                         uint32_t b0, uint32_t b1) {
    asm volatile(
        "mma.sync.aligned.m16n8k16.row.col.f32.bf16.bf16.f32 "
        "{%0,%1,%2,%3}, {%4,%5,%6,%7}, {%8,%9}, {%0,%1,%2,%3};"
        : "+f"(c[0]), "+f"(c[1]), "+f"(c[2]), "+f"(c[3])
        : "r"(a0), "r"(a1), "r"(a2), "r"(a3), "r"(b0), "r"(b1));
}
// fp16 mma (projection GEMMs)
__device__ __forceinline__ void mma16816h(float* c, uint32_t a0, uint32_t a1,
                                          uint32_t a2, uint32_t a3,
                                          uint32_t b0, uint32_t b1) {
    asm volatile(
        "mma.sync.aligned.m16n8k16.row.col.f32.f16.f16.f32 "
        "{%0,%1,%2,%3}, {%4,%5,%6,%7}, {%8,%9}, {%0,%1,%2,%3};"
        : "+f"(c[0]), "+f"(c[1]), "+f"(c[2]), "+f"(c[3])
        : "r"(a0), "r"(a1), "r"(a2), "r"(a3), "r"(b0), "r"(b1));
}
__device__ __forceinline__ float ex2(float x) {
    float r;
    asm("ex2.approx.f32 %0, %1;" : "=f"(r) : "f"(x));
    return r;
}

// ---- bf16 split helpers (flash) ----
__device__ __forceinline__ void split4(float4 v, uint32_t& h0, uint32_t& h1,
                                       uint32_t& l0, uint32_t& l1) {
    __nv_bfloat162 a = __floats2bfloat162_rn(v.x, v.y);
    __nv_bfloat162 b = __floats2bfloat162_rn(v.z, v.w);
    __nv_bfloat162 ra = __floats2bfloat162_rn(v.x - __bfloat162float(a.x),
                                              v.y - __bfloat162float(a.y));
    __nv_bfloat162 rb = __floats2bfloat162_rn(v.z - __bfloat162float(b.x),
                                              v.w - __bfloat162float(b.y));
    h0 = *(uint32_t*)&a; h1 = *(uint32_t*)&b;
    l0 = *(uint32_t*)&ra; l1 = *(uint32_t*)&rb;
}
__device__ __forceinline__ uint32_t pack_hi(float x, float y) {
    __nv_bfloat162 h = __floats2bfloat162_rn(x, y);
    return *(uint32_t*)&h;
}
__device__ __forceinline__ uint32_t pack_lo(float x, float y, uint32_t hbits) {
    __nv_bfloat162 h = *(__nv_bfloat162*)&hbits;
    __nv_bfloat162 l = __floats2bfloat162_rn(x - __bfloat162float(h.x),
                                             y - __bfloat162float(h.y));
    return *(uint32_t*)&l;
}
// ---- fp16 split helpers (GEMMs) ----
__device__ __forceinline__ void split4h(float4 v, uint32_t& h0, uint32_t& h1,
                                        uint32_t& l0, uint32_t& l1) {
    __half2 a = __floats2half2_rn(v.x, v.y);
    __half2 b = __floats2half2_rn(v.z, v.w);
    __half2 ra = __floats2half2_rn(v.x - __half2float(a.x),
                                   v.y - __half2float(a.y));
    __half2 rb = __floats2half2_rn(v.z - __half2float(b.x),
                                   v.w - __half2float(b.y));
    h0 = *(uint32_t*)&a; h1 = *(uint32_t*)&b;
    l0 = *(uint32_t*)&ra; l1 = *(uint32_t*)&rb;
}
__device__ __forceinline__ void round4h(float4 v, uint32_t& h0, uint32_t& h1) {
    __half2 a = __floats2half2_rn(v.x, v.y);
    __half2 b = __floats2half2_rn(v.z, v.w);
    h0 = *(uint32_t*)&a; h1 = *(uint32_t*)&b;
}

// ======== fp16 2-term GEMM body: C[M,N] = A[M,K] @ W[K,N] ==================
// A split exactly into fp16 hi/lo; W rounded once to fp16.
// mode 0: C row-major [M,N].  mode 1: C as [B, H, T, HD] head layout.
#define SP  40
#define BSP 136

__device__ __forceinline__ void gemm_body(
    const float* __restrict__ A, const float* __restrict__ W,
    float* __restrict__ C, int N, int K, int mode, int H, int m0, int n0)
{
    __shared__ __align__(16) uint16_t sAh[128 * SP];
    __shared__ __align__(16) uint16_t sAl[128 * SP];
    __shared__ __align__(16) uint16_t sBh[32 * BSP];

    const uint32_t uAh = smem_u32(sAh), uAl = smem_u32(sAl);
    const uint32_t uBh = smem_u32(sBh);

    int tid = threadIdx.x;
    int wid = tid >> 5, lane = tid & 31;
    int wm = wid >> 2, wn = wid & 3;

    int arow = tid >> 1;
    int acb  = (tid & 1) << 4;
    int bk0  = tid >> 5;
    int bn4  = (tid & 31) << 2;

    const float* apg = A + (size_t)(m0 + arow) * K + acb;
    const float* bpg = W + (size_t)bk0 * N + n0 + bn4;

    float acc[4][4][4];
    #pragma unroll
    for (int i = 0; i < 4; ++i)
        #pragma unroll
        for (int j = 0; j < 4; ++j)
            #pragma unroll
            for (int e = 0; e < 4; ++e) acc[i][j][e] = 0.f;

    for (int k0 = 0; k0 < K; k0 += 32) {
        #pragma unroll
        for (int c = 0; c < 4; ++c) {
            float4 v = *(const float4*)(apg + k0 + (c << 2));
            uint32_t h0, h1, l0, l1;
            split4h(v, h0, h1, l0, l1);
            uint32_t off = (uint32_t)(arow * SP + acb + (c << 2)) << 1;
            *(uint32_t*)((char*)sAh + off)     = h0;
            *(uint32_t*)((char*)sAh + off + 4) = h1;
            *(uint32_t*)((char*)sAl + off)     = l0;
            *(uint32_t*)((char*)sAl + off + 4) = l1;
        }
        #pragma unroll
        for (int it = 0; it < 4; ++it) {
            float4 v = *(const float4*)(bpg + (size_t)(k0 + (it << 3)) * N);
            uint32_t h0, h1;
            round4h(v, h0, h1);
            uint32_t off = (uint32_t)((bk0 + (it << 3)) * BSP + bn4) << 1;
            *(uint32_t*)((char*)sBh + off)     = h0;
            *(uint32_t*)((char*)sBh + off + 4) = h1;
        }
        __syncthreads();

        int r16 = lane & 15, hsel = lane >> 4;
        #pragma unroll
        for (int ks = 0; ks < 2; ++ks) {
            uint32_t bh[2][4];
            #pragma unroll
            for (int j2 = 0; j2 < 2; ++j2) {
                uint32_t boff = (uint32_t)((ks * 16 + r16) * BSP +
                                           (wn << 5) + (j2 << 4) + (hsel << 3)) << 1;
                ldm_x4_trans(bh[j2][0], bh[j2][1], bh[j2][2], bh[j2][3], uBh + boff);
            }
            #pragma unroll
            for (int i = 0; i < 4; ++i) {
                uint32_t aoff = (uint32_t)(((wm << 6) + (i << 4) + r16) * SP +
                                           ks * 16 + (hsel << 3)) << 1;
                uint32_t ah0, ah1, ah2, ah3, al0, al1, al2, al3;
                ldm_x4(ah0, ah1, ah2, ah3, uAh + aoff);
                ldm_x4(al0, al1, al2, al3, uAl + aoff);
                #pragma unroll
                for (int j2 = 0; j2 < 2; ++j2) {
                    mma16816h(acc[i][2*j2],   ah0, ah1, ah2, ah3, bh[j2][0], bh[j2][1]);
                    mma16816h(acc[i][2*j2+1], ah0, ah1, ah2, ah3, bh[j2][2], bh[j2][3]);
                    mma16816h(acc[i][2*j2],   al0, al1, al2, al3, bh[j2][0], bh[j2][1]);
                    mma16816h(acc[i][2*j2+1], al0, al1, al2, al3, bh[j2][2], bh[j2][3]);
                }
            }
        }
        __syncthreads();
    }

    int g = lane >> 2, q = lane & 3;
    #pragma unroll
    for (int i = 0; i < 4; ++i) {
        #pragma unroll
        for (int half = 0; half < 2; ++half) {
            int m = m0 + (wm << 6) + (i << 4) + g + (half << 3);
            float* dst;
            if (mode == 0) {
                dst = C + (size_t)m * N + n0;
            } else {
                int b = m >> 11, t = m & (Tt - 1), h = n0 >> 7;
                dst = C + (((size_t)(b * H + h) * Tt + t) << 7);
            }
            #pragma unroll
            for (int j = 0; j < 4; ++j) {
                int nl = (wn << 5) + (j << 3) + (q << 1);
                float2 v;
                v.x = acc[i][j][half * 2];
                v.y = acc[i][j][half * 2 + 1];
                *(float2*)(dst + nl) = v;
            }
        }
    }
}

// ---- fused QKV projection: one launch, W selected by blockIdx.x ----
__global__ __launch_bounds__(256, 2) void qkv_gemm_kernel(
    const float* __restrict__ A,
    const float* __restrict__ Wq, const float* __restrict__ Wk,
    const float* __restrict__ Wv,
    float* __restrict__ Qo, float* __restrict__ Ko, float* __restrict__ Vo)
{
    int x = blockIdx.x;
    int m0 = blockIdx.y << 7;
    const float* W; float* C; int N, H, n0;
    if (x < 16)      { W = Wq; C = Qo; N = NH*HD;  H = NH;  n0 = x << 7; }
    else if (x < 20) { W = Wk; C = Ko; N = KVH*HD; H = KVH; n0 = (x - 16) << 7; }
    else             { W = Wv; C = Vo; N = KVH*HD; H = KVH; n0 = (x - 20) << 7; }
    gemm_body(A, W, C, N, HIDD, 1, H, m0, n0);
}

// ---- generic GEMM (output projection) ----
__global__ __launch_bounds__(256, 2) void tc_gemm_kernel(
    const float* __restrict__ A, const float* __restrict__ W,
    float* __restrict__ C, int N, int K, int mode, int H)
{
    gemm_body(A, W, C, N, K, mode, H, blockIdx.y << 7, blockIdx.x << 7);
}

// ---------------- RoPE (in-place on [B,H,T,HD]) ----------------
__global__ void rope_kernel(float* __restrict__ X, const float* __restrict__ cs,
                            const float* __restrict__ sn, int total)
{
    int i = blockIdx.x * blockDim.x + threadIdx.x;
    if (i >= total) return;
    int d = i & 63;
    int rest = i >> 6;
    int t = rest & (Tt - 1);
    float* row = X + ((size_t)rest << 7);
    float x1 = row[d], x2 = row[d + 64];
    float c1 = cs[(t << 7) + d],      s1 = sn[(t << 7) + d];
    float c2 = cs[(t << 7) + d + 64], s2 = sn[(t << 7) + d + 64];
    row[d]      = x1 * c1 - x2 * s1;
    row[d + 64] = x2 * c2 + x1 * s2;
}

// ========== Flash attention on mma.sync (causal, GQA, 3-term bf16) =========
#define FSP 136

__global__ __launch_bounds__(256, 1) void flash_mma_kernel(
    const float* __restrict__ Q, const float* __restrict__ K,
    const float* __restrict__ V, float* __restrict__ ctx)
{
    extern __shared__ char fsm[];
    uint16_t* Qh = (uint16_t*)fsm;
    uint16_t* Ql = Qh + 128 * FSP;
    uint16_t* Kh = Ql + 128 * FSP;
    uint16_t* Kl = Kh + 64 * FSP;
    uint16_t* Vh = Kl + 64 * FSP;
    uint16_t* Vl = Vh + 64 * FSP;
    const uint32_t uQh = smem_u32(Qh), uQl = smem_u32(Ql);
    const uint32_t uKh = smem_u32(Kh), uKl = smem_u32(Kl);
    const uint32_t uVh = smem_u32(Vh), uVl = smem_u32(Vl);

    int tid = threadIdx.x, wid = tid >> 5, lane = tid & 31;
    int g = lane >> 2, qd = lane & 3;
    int r16 = lane & 15, hsel = lane >> 4;
    int qt = gridDim.x - 1 - blockIdx.x;
    int bh = blockIdx.y;
    int b = bh >> 4, h = bh & 15, kvh = h >> 2;

    const float* Qp = Q + (((size_t)(b * NH + h) * Tt + qt * 128) << 7);
    const float* Kp = K + (((size_t)(b * KVH + kvh) * Tt) << 7);
    const float* Vp = V + (((size_t)(b * KVH + kvh) * Tt) << 7);

    {
        int row = tid >> 1, cb = (tid & 1) << 6;
        const float* qp = Qp + ((size_t)row << 7) + cb;
        #pragma unroll
        for (int i = 0; i < 16; ++i) {
            float4 v = *(const float4*)(qp + (i << 2));
            uint32_t h0, h1, l0, l1;
            split4(v, h0, h1, l0, l1);
            uint32_t off = (uint32_t)(row * FSP + cb + (i << 2)) << 1;
            *(uint32_t*)((char*)Qh + off)     = h0;
            *(uint32_t*)((char*)Qh + off + 4) = h1;
            *(uint32_t*)((char*)Ql + off)     = l0;
            *(uint32_t*)((char*)Ql + off + 4) = l1;
        }
    }

    float o[16][4];
    #pragma unroll
    for (int i = 0; i < 16; ++i)
        #pragma unroll
        for (int e = 0; e < 4; ++e) o[i][e] = 0.f;
    float m0 = -1e30f, m1 = -1e30f, l0 = 0.f, l1 = 0.f;
    const float alpha = 0.08838834764831845f * 1.4426950408889634f;

    int qbase = qt * 128 + wid * 16;
    int ntiles = 2 * qt + 2;

    int srow = tid >> 2, scb = (tid & 3) << 5;

    float4 kr[8], vr[8];
    {
        const float* kp = Kp + ((size_t)srow << 7) + scb;
        const float* vp = Vp + ((size_t)srow << 7) + scb;
        #pragma unroll
        for (int i = 0; i < 8; ++i) {
            kr[i] = *(const float4*)(kp + (i << 2));
            vr[i] = *(const float4*)(vp + (i << 2));
        }
    }

    for (int jt = 0; jt < ntiles; ++jt) {
        __syncthreads();
        #pragma unroll
        for (int i = 0; i < 8; ++i) {
            uint32_t off = (uint32_t)(srow * FSP + scb + (i << 2)) << 1;
            uint32_t h0, h1, lo0, lo1;
            split4(kr[i], h0, h1, lo0, lo1);
            *(uint32_t*)((char*)Kh + off)     = h0;
            *(uint32_t*)((char*)Kh + off + 4) = h1;
            *(uint32_t*)((char*)Kl + off)     = lo0;
            *(uint32_t*)((char*)Kl + off + 4) = lo1;
            split4(vr[i], h0, h1, lo0, lo1);
            *(uint32_t*)((char*)Vh + off)     = h0;
            *(uint32_t*)((char*)Vh + off + 4) = h1;
            *(uint32_t*)((char*)Vl + off)     = lo0;
            *(uint32_t*)((char*)Vl + off + 4) = lo1;
        }
        __syncthreads();

        if (jt + 1 < ntiles) {
            const float* kp = Kp + ((size_t)((jt + 1) * 64 + srow) << 7) + scb;
            const float* vp = Vp + ((size_t)((jt + 1) * 64 + srow) << 7) + scb;
            #pragma unroll
            for (int i = 0; i < 8; ++i) {
                kr[i] = *(const float4*)(kp + (i << 2));
                vr[i] = *(const float4*)(vp + (i << 2));
            }
        }

        float s[8][4];
        #pragma unroll
        for (int t8 = 0; t8 < 8; ++t8)
            #pragma unroll
            for (int e = 0; e < 4; ++e) s[t8][e] = 0.f;

        #pragma unroll
        for (int ks = 0; ks < 8; ++ks) {
            uint32_t aoff = (uint32_t)((wid * 16 + r16) * FSP + ks * 16 + (hsel << 3)) << 1;
            uint32_t ah0, ah1, ah2, ah3, al0, al1, al2, al3;
            ldm_x4(ah0, ah1, ah2, ah3, uQh + aoff);
            ldm_x4(al0, al1, al2, al3, uQl + aoff);
            #pragma unroll
            for (int nt = 0; nt < 4; ++nt) {
                uint32_t koff = (uint32_t)((nt * 16 + r16) * FSP + ks * 16 + (hsel << 3)) << 1;
                uint32_t kh0, kh1, kh2, kh3, kl0, kl1, kl2, kl3;
                ldm_x4(kh0, kh1, kh2, kh3, uKh + koff);
                ldm_x4(kl0, kl1, kl2, kl3, uKl + koff);
                mma16816(s[2*nt],   ah0, ah1, ah2, ah3, kh0, kh2);
                mma16816(s[2*nt+1], ah0, ah1, ah2, ah3, kh1, kh3);
                mma16816(s[2*nt],   ah0, ah1, ah2, ah3, kl0, kl2);
                mma16816(s[2*nt+1], ah0, ah1, ah2, ah3, kl1, kl3);
                mma16816(s[2*nt],   al0, al1, al2, al3, kh0, kh2);
                mma16816(s[2*nt+1], al0, al1, al2, al3, kh1, kh3);
            }
        }

        int kvb = jt * 64;
        int qr0 = qbase + g;
        bool needmask = (kvb + 63 > qbase);
        #pragma unroll
        for (int t8 = 0; t8 < 8; ++t8) {
            #pragma unroll
            for (int e = 0; e < 4; ++e) {
                float val = s[t8][e] * alpha;
                if (needmask) {
                    int col = kvb + t8 * 8 + qd * 2 + (e & 1);
                    int row = (e < 2) ? qr0 : qr0 + 8;
                    if (col > row) val = -1e30f;
                }
                s[t8][e] = val;
            }
        }

        float tm0 = -1e30f, tm1 = -1e30f;
        #pragma unroll
        for (int t8 = 0; t8 < 8; ++t8) {
            tm0 = fmaxf(tm0, fmaxf(s[t8][0], s[t8][1]));
            tm1 = fmaxf(tm1, fmaxf(s[t8][2], s[t8][3]));
        }
        tm0 = fmaxf(tm0, __shfl_xor_sync(0xffffffffu, tm0, 1));
        tm0 = fmaxf(tm0, __shfl_xor_sync(0xffffffffu, tm0, 2));
        tm1 = fmaxf(tm1, __shfl_xor_sync(0xffffffffu, tm1, 1));
        tm1 = fmaxf(tm1, __shfl_xor_sync(0xffffffffu, tm1, 2));
        float nm0 = fmaxf(m0, tm0), nm1 = fmaxf(m1, tm1);
        float c0 = ex2(m0 - nm0), c1 = ex2(m1 - nm1);
        m0 = nm0; m1 = nm1;

        float ps0 = 0.f, ps1 = 0.f;
        #pragma unroll
        for (int t8 = 0; t8 < 8; ++t8) {
            s[t8][0] = ex2(s[t8][0] - nm0);
            s[t8][1] = ex2(s[t8][1] - nm0);
            s[t8][2] = ex2(s[t8][2] - nm1);
            s[t8][3] = ex2(s[t8][3] - nm1);
            ps0 += s[t8][0] + s[t8][1];
            ps1 += s[t8][2] + s[t8][3];
        }
        ps0 += __shfl_xor_sync(0xffffffffu, ps0, 1);
        ps0 += __shfl_xor_sync(0xffffffffu, ps0, 2);
        ps1 += __shfl_xor_sync(0xffffffffu, ps1, 1);
        ps1 += __shfl_xor_sync(0xffffffffu, ps1, 2);
        l0 = l0 * c0 + ps0;
        l1 = l1 * c1 + ps1;

        #pragma unroll
        for (int dt = 0; dt < 16; ++dt) {
            o[dt][0] *= c0; o[dt][1] *= c0;
            o[dt][2] *= c1; o[dt][3] *= c1;
        }

        #pragma unroll
        for (int j = 0; j < 4; ++j) {
            uint32_t ph0 = pack_hi(s[2*j][0],   s[2*j][1]);
            uint32_t ph1 = pack_hi(s[2*j][2],   s[2*j][3]);
            uint32_t ph2 = pack_hi(s[2*j+1][0], s[2*j+1][1]);
            uint32_t ph3 = pack_hi(s[2*j+1][2], s[2*j+1][3]);
            uint32_t pl0 = pack_lo(s[2*j][0],   s[2*j][1],   ph0);
            uint32_t pl1 = pack_lo(s[2*j][2],   s[2*j][3],   ph1);
            uint32_t pl2 = pack_lo(s[2*j+1][0], s[2*j+1][1], ph2);
            uint32_t pl3 = pack_lo(s[2*j+1][2], s[2*j+1][3], ph3);
            #pragma unroll
            for (int dt = 0; dt < 8; ++dt) {
                uint32_t voff = (uint32_t)((j * 16 + r16) * FSP + dt * 16 + (hsel << 3)) << 1;
                uint32_t vh0, vh1, vh2, vh3, vl0, vl1, vl2, vl3;
                ldm_x4_trans(vh0, vh1, vh2, vh3, uVh + voff);
                ldm_x4_trans(vl0, vl1, vl2, vl3, uVl + voff);
                mma16816(o[2*dt],   ph0, ph1, ph2, ph3, vh0, vh1);
                mma16816(o[2*dt+1], ph0, ph1, ph2, ph3, vh2, vh3);
                mma16816(o[2*dt],   pl0, pl1, pl2, pl3, vh0, vh1);
                mma16816(o[2*dt+1], pl0, pl1, pl2, pl3, vh2, vh3);
                mma16816(o[2*dt],   ph0, ph1, ph2, ph3, vl0, vl1);
                mma16816(o[2*dt+1], ph0, ph1, ph2, ph3, vl2, vl3);
            }
        }
    }

    float li0 = 1.f / l0, li1 = 1.f / l1;
    int t0 = qbase + g;
    float* dst0 = ctx + (size_t)(b * Tt + t0) * HIDD + h * HD;
    float* dst1 = ctx + (size_t)(b * Tt + t0 + 8) * HIDD + h * HD;
    #pragma unroll
    for (int dt = 0; dt < 16; ++dt) {
        int col = dt * 8 + qd * 2;
        float2 w0 = make_float2(o[dt][0] * li0, o[dt][1] * li0);
        float2 w1 = make_float2(o[dt][2] * li1, o[dt][3] * li1);
        *(float2*)(dst0 + col) = w0;
        *(float2*)(dst1 + col) = w1;
    }
}

// ---------------- launch ----------------
extern "C" void kernel_launch(void* const* d_in, const int* in_sizes, int n_in,
                              void* d_out, int out_size)
{
    const float* hs   = (const float*)d_in[0];
    const float* cosp = (const float*)d_in[2];
    const float* sinp = (const float*)d_in[3];
    const float* Wq   = (const float*)d_in[4];
    const float* Wk   = (const float*)d_in[5];
    const float* Wv   = (const float*)d_in[6];
    const float* Wo   = (const float*)d_in[7];
    float* out = (float*)d_out;

    float *pQ, *pK, *pV, *pC;
    cudaGetSymbolAddress((void**)&pQ, g_Q);
    cudaGetSymbolAddress((void**)&pK, g_K);
    cudaGetSymbolAddress((void**)&pV, g_V);
    cudaGetSymbolAddress((void**)&pC, g_ctx);

    // Fused QKV projection (fp16 2-term)
    qkv_gemm_kernel<<<dim3(24, 32), 256>>>(hs, Wq, Wk, Wv, pQ, pK, pV);

    // RoPE on Q and K
    int totQ = Bb * NH  * Tt * 64;
    int totK = Bb * KVH * Tt * 64;
    rope_kernel<<<totQ / 256, 256>>>(pQ, cosp, sinp, totQ);
    rope_kernel<<<totK / 256, 256>>>(pK, cosp, sinp, totK);

    // Flash attention on mma.sync (bf16 3-term, register-preloaded pipeline)
    size_t fsh = (size_t)(2 * 128 * FSP + 4 * 64 * FSP) * sizeof(uint16_t); // 139264
    cudaFuncSetAttribute(flash_mma_kernel, cudaFuncAttributeMaxDynamicSharedMemorySize, (int)fsh);
    flash_mma_kernel<<<dim3(Tt/128, Bb*NH), 256, fsh>>>(pQ, pK, pV, pC);

    // Output projection (fp16 2-term) -> d_out
    tc_gemm_kernel<<<dim3(16, 32), 256>>>(pC, Wo, out, HIDD, HIDD, 0, 0);
}

// round 11
// speedup vs baseline: 1.9216x; 1.1602x over previous
#include <cuda_runtime.h>
#include <cuda_bf16.h>
#include <cuda_fp16.h>
#include <cstdint>
#include <math.h>

#define Bb   2
#define Tt   2048
#define HIDD 2048
#define NH   16
#define KVH  4
#define HD   128
#define Mrows (Bb*Tt)

// ---------------- scratch (device globals: allocation-free) ----------------
__device__ float g_Q[(size_t)Bb*NH*Tt*HD];    // [B, NH, T, HD]
__device__ float g_K[(size_t)Bb*KVH*Tt*HD];   // [B, KVH, T, HD]
__device__ float g_V[(size_t)Bb*KVH*Tt*HD];   // [B, KVH, T, HD]
__device__ float g_ctx[(size_t)Bb*Tt*HIDD];   // [B*T, HID]

// ================= mma.sync helpers (compute_103-safe) =====================
__device__ __forceinline__ uint32_t smem_u32(const void* p) {
    uint32_t a;
    asm("{ .reg .u64 t; cvta.to.shared.u64 t, %1; cvt.u32.u64 %0, t; }" : "=r"(a) : "l"(p));
    return a;
}
__device__ __forceinline__ void ldm_x4(uint32_t& r0, uint32_t& r1, uint32_t& r2,
                                       uint32_t& r3, uint32_t addr) {
    asm volatile("ldmatrix.sync.aligned.m8n8.x4.shared.b16 {%0,%1,%2,%3}, [%4];"
                 : "=r"(r0), "=r"(r1), "=r"(r2), "=r"(r3) : "r"(addr));
}
__device__ __forceinline__ void ldm_x4_trans(uint32_t& r0, uint32_t& r1, uint32_t& r2,
                                             uint32_t& r3, uint32_t addr) {
    asm volatile("ldmatrix.sync.aligned.m8n8.x4.trans.shared.b16 {%0,%1,%2,%3}, [%4];"
                 : "=r"(r0), "=r"(r1), "=r"(r2), "=r"(r3) : "r"(addr));
}
// fp16 mma
__device__ __forceinline__ void mma16816h(float* c, uint32_t a0, uint32_t a1,
                                          uint32_t a2, uint32_t a3,
                                          uint32_t b0, uint32_t b1) {
    asm volatile(
        "mma.sync.aligned.m16n8k16.row.col.f32.f16.f16.f32 "
        "{%0,%1,%2,%3}, {%4,%5,%6,%7}, {%8,%9}, {%0,%1,%2,%3};"
        : "+f"(c[0]), "+f"(c[1]), "+f"(c[2]), "+f"(c[3])
        : "r"(a0), "r"(a1), "r"(a2), "r"(a3), "r"(b0), "r"(b1));
}
__device__ __forceinline__ float ex2(float x) {
    float r;
    asm("ex2.approx.f32 %0, %1;" : "=f"(r) : "f"(x));
    return r;
}

// ---- fp16 split helpers ----
__device__ __forceinline__ void split4h(float4 v, uint32_t& h0, uint32_t& h1,
                                        uint32_t& l0, uint32_t& l1) {
    __half2 a = __floats2half2_rn(v.x, v.y);
    __half2 b = __floats2half2_rn(v.z, v.w);
    __half2 ra = __floats2half2_rn(v.x - __half2float(a.x),
                                   v.y - __half2float(a.y));
    __half2 rb = __floats2half2_rn(v.z - __half2float(b.x),
                                   v.w - __half2float(b.y));
    h0 = *(uint32_t*)&a; h1 = *(uint32_t*)&b;
    l0 = *(uint32_t*)&ra; l1 = *(uint32_t*)&rb;
}
__device__ __forceinline__ void round4h(float4 v, uint32_t& h0, uint32_t& h1) {
    __half2 a = __floats2half2_rn(v.x, v.y);
    __half2 b = __floats2half2_rn(v.z, v.w);
    h0 = *(uint32_t*)&a; h1 = *(uint32_t*)&b;
}
__device__ __forceinline__ uint32_t pack_h(float x, float y) {
    __half2 h = __floats2half2_rn(x, y);
    return *(uint32_t*)&h;
}

// ======== fp16 2-term GEMM body: C[M,N] = A[M,K] @ W[K,N] ==================
#define SP  40
#define BSP 136

__device__ __forceinline__ void gemm_body(
    const float* __restrict__ A, const float* __restrict__ W,
    float* __restrict__ C, int N, int K, int mode, int H, int m0, int n0)
{
    __shared__ __align__(16) uint16_t sAh[128 * SP];
    __shared__ __align__(16) uint16_t sAl[128 * SP];
    __shared__ __align__(16) uint16_t sBh[32 * BSP];

    const uint32_t uAh = smem_u32(sAh), uAl = smem_u32(sAl);
    const uint32_t uBh = smem_u32(sBh);

    int tid = threadIdx.x;
    int wid = tid >> 5, lane = tid & 31;
    int wm = wid >> 2, wn = wid & 3;

    int arow = tid >> 1;
    int acb  = (tid & 1) << 4;
    int bk0  = tid >> 5;
    int bn4  = (tid & 31) << 2;

    const float* apg = A + (size_t)(m0 + arow) * K + acb;
    const float* bpg = W + (size_t)bk0 * N + n0 + bn4;

    float acc[4][4][4];
    #pragma unroll
    for (int i = 0; i < 4; ++i)
        #pragma unroll
        for (int j = 0; j < 4; ++j)
            #pragma unroll
            for (int e = 0; e < 4; ++e) acc[i][j][e] = 0.f;

    for (int k0 = 0; k0 < K; k0 += 32) {
        #pragma unroll
        for (int c = 0; c < 4; ++c) {
            float4 v = *(const float4*)(apg + k0 + (c << 2));
            uint32_t h0, h1, l0, l1;
            split4h(v, h0, h1, l0, l1);
            uint32_t off = (uint32_t)(arow * SP + acb + (c << 2)) << 1;
            *(uint32_t*)((char*)sAh + off)     = h0;
            *(uint32_t*)((char*)sAh + off + 4) = h1;
            *(uint32_t*)((char*)sAl + off)     = l0;
            *(uint32_t*)((char*)sAl + off + 4) = l1;
        }
        #pragma unroll
        for (int it = 0; it < 4; ++it) {
            float4 v = *(const float4*)(bpg + (size_t)(k0 + (it << 3)) * N);
            uint32_t h0, h1;
            round4h(v, h0, h1);
            uint32_t off = (uint32_t)((bk0 + (it << 3)) * BSP + bn4) << 1;
            *(uint32_t*)((char*)sBh + off)     = h0;
            *(uint32_t*)((char*)sBh + off + 4) = h1;
        }
        __syncthreads();

        int r16 = lane & 15, hsel = lane >> 4;
        #pragma unroll
        for (int ks = 0; ks < 2; ++ks) {
            uint32_t bh[2][4];
            #pragma unroll
            for (int j2 = 0; j2 < 2; ++j2) {
                uint32_t boff = (uint32_t)((ks * 16 + r16) * BSP +
                                           (wn << 5) + (j2 << 4) + (hsel << 3)) << 1;
                ldm_x4_trans(bh[j2][0], bh[j2][1], bh[j2][2], bh[j2][3], uBh + boff);
            }
            #pragma unroll
            for (int i = 0; i < 4; ++i) {
                uint32_t aoff = (uint32_t)(((wm << 6) + (i << 4) + r16) * SP +
                                           ks * 16 + (hsel << 3)) << 1;
                uint32_t ah0, ah1, ah2, ah3, al0, al1, al2, al3;
                ldm_x4(ah0, ah1, ah2, ah3, uAh + aoff);
                ldm_x4(al0, al1, al2, al3, uAl + aoff);
                #pragma unroll
                for (int j2 = 0; j2 < 2; ++j2) {
                    mma16816h(acc[i][2*j2],   ah0, ah1, ah2, ah3, bh[j2][0], bh[j2][1]);
                    mma16816h(acc[i][2*j2+1], ah0, ah1, ah2, ah3, bh[j2][2], bh[j2][3]);
                    mma16816h(acc[i][2*j2],   al0, al1, al2, al3, bh[j2][0], bh[j2][1]);
                    mma16816h(acc[i][2*j2+1], al0, al1, al2, al3, bh[j2][2], bh[j2][3]);
                }
            }
        }
        __syncthreads();
    }

    int g = lane >> 2, q = lane & 3;
    #pragma unroll
    for (int i = 0; i < 4; ++i) {
        #pragma unroll
        for (int half = 0; half < 2; ++half) {
            int m = m0 + (wm << 6) + (i << 4) + g + (half << 3);
            float* dst;
            if (mode == 0) {
                dst = C + (size_t)m * N + n0;
            } else {
                int b = m >> 11, t = m & (Tt - 1), h = n0 >> 7;
                dst = C + (((size_t)(b * H + h) * Tt + t) << 7);
            }
            #pragma unroll
            for (int j = 0; j < 4; ++j) {
                int nl = (wn << 5) + (j << 3) + (q << 1);
                float2 v;
                v.x = acc[i][j][half * 2];
                v.y = acc[i][j][half * 2 + 1];
                *(float2*)(dst + nl) = v;
            }
        }
    }
}

// ---- fused QKV projection: one launch, W selected by blockIdx.x ----
__global__ __launch_bounds__(256, 2) void qkv_gemm_kernel(
    const float* __restrict__ A,
    const float* __restrict__ Wq, const float* __restrict__ Wk,
    const float* __restrict__ Wv,
    float* __restrict__ Qo, float* __restrict__ Ko, float* __restrict__ Vo)
{
    int x = blockIdx.x;
    int m0 = blockIdx.y << 7;
    const float* W; float* C; int N, H, n0;
    if (x < 16)      { W = Wq; C = Qo; N = NH*HD;  H = NH;  n0 = x << 7; }
    else if (x < 20) { W = Wk; C = Ko; N = KVH*HD; H = KVH; n0 = (x - 16) << 7; }
    else             { W = Wv; C = Vo; N = KVH*HD; H = KVH; n0 = (x - 20) << 7; }
    gemm_body(A, W, C, N, HIDD, 1, H, m0, n0);
}

// ---- generic GEMM (output projection) ----
__global__ __launch_bounds__(256, 2) void tc_gemm_kernel(
    const float* __restrict__ A, const float* __restrict__ W,
    float* __restrict__ C, int N, int K, int mode, int H)
{
    gemm_body(A, W, C, N, K, mode, H, blockIdx.y << 7, blockIdx.x << 7);
}

// ---------------- RoPE (in-place on [B,H,T,HD]) ----------------
__global__ void rope_kernel(float* __restrict__ X, const float* __restrict__ cs,
                            const float* __restrict__ sn, int total)
{
    int i = blockIdx.x * blockDim.x + threadIdx.x;
    if (i >= total) return;
    int d = i & 63;
    int rest = i >> 6;
    int t = rest & (Tt - 1);
    float* row = X + ((size_t)rest << 7);
    float x1 = row[d], x2 = row[d + 64];
    float c1 = cs[(t << 7) + d],      s1 = sn[(t << 7) + d];
    float c2 = cs[(t << 7) + d + 64], s2 = sn[(t << 7) + d + 64];
    row[d]      = x1 * c1 - x2 * s1;
    row[d + 64] = x2 * c2 + x1 * s2;
}

// ========== Flash attention (fp16: 2-term S, 1-term PV; causal, GQA) =======
// CTA: 256 threads (8 warps), Q tile 128 rows (16 per warp), KV tile 64.
// Q split exactly into fp16 hi/lo; K,V rounded once to fp16.
// K/V global loads for tile jt+1 preloaded into registers during tile jt.
#define FSP 136

__global__ __launch_bounds__(256, 1) void flash_mma_kernel(
    const float* __restrict__ Q, const float* __restrict__ K,
    const float* __restrict__ V, float* __restrict__ ctx)
{
    extern __shared__ char fsm[];
    uint16_t* Qh = (uint16_t*)fsm;
    uint16_t* Ql = Qh + 128 * FSP;
    uint16_t* Kh = Ql + 128 * FSP;
    uint16_t* Vh = Kh + 64 * FSP;
    const uint32_t uQh = smem_u32(Qh), uQl = smem_u32(Ql);
    const uint32_t uKh = smem_u32(Kh), uVh = smem_u32(Vh);

    int tid = threadIdx.x, wid = tid >> 5, lane = tid & 31;
    int g = lane >> 2, qd = lane & 3;
    int r16 = lane & 15, hsel = lane >> 4;
    int qt = gridDim.x - 1 - blockIdx.x;
    int bh = blockIdx.y;
    int b = bh >> 4, h = bh & 15, kvh = h >> 2;

    const float* Qp = Q + (((size_t)(b * NH + h) * Tt + qt * 128) << 7);
    const float* Kp = K + (((size_t)(b * KVH + kvh) * Tt) << 7);
    const float* Vp = V + (((size_t)(b * KVH + kvh) * Tt) << 7);

    // ---- stage Q tile (128x128 fp32 -> fp16 hi/lo, exact split) ----
    {
        int row = tid >> 1, cb = (tid & 1) << 6;
        const float* qp = Qp + ((size_t)row << 7) + cb;
        #pragma unroll
        for (int i = 0; i < 16; ++i) {
            float4 v = *(const float4*)(qp + (i << 2));
            uint32_t h0, h1, l0, l1;
            split4h(v, h0, h1, l0, l1);
            uint32_t off = (uint32_t)(row * FSP + cb + (i << 2)) << 1;
            *(uint32_t*)((char*)Qh + off)     = h0;
            *(uint32_t*)((char*)Qh + off + 4) = h1;
            *(uint32_t*)((char*)Ql + off)     = l0;
            *(uint32_t*)((char*)Ql + off + 4) = l1;
        }
    }

    float o[16][4];
    #pragma unroll
    for (int i = 0; i < 16; ++i)
        #pragma unroll
        for (int e = 0; e < 4; ++e) o[i][e] = 0.f;
    float m0 = -1e30f, m1 = -1e30f, l0 = 0.f, l1 = 0.f;
    const float alpha = 0.08838834764831845f * 1.4426950408889634f;

    int qbase = qt * 128 + wid * 16;
    int ntiles = 2 * qt + 2;

    int srow = tid >> 2, scb = (tid & 3) << 5;

    float4 kr[8], vr[8];
    {
        const float* kp = Kp + ((size_t)srow << 7) + scb;
        const float* vp = Vp + ((size_t)srow << 7) + scb;
        #pragma unroll
        for (int i = 0; i < 8; ++i) {
            kr[i] = *(const float4*)(kp + (i << 2));
            vr[i] = *(const float4*)(vp + (i << 2));
        }
    }

    for (int jt = 0; jt < ntiles; ++jt) {
        __syncthreads();
        // ---- store+convert preloaded K,V tile (fp16, rounded once) ----
        #pragma unroll
        for (int i = 0; i < 8; ++i) {
            uint32_t off = (uint32_t)(srow * FSP + scb + (i << 2)) << 1;
            uint32_t h0, h1;
            round4h(kr[i], h0, h1);
            *(uint32_t*)((char*)Kh + off)     = h0;
            *(uint32_t*)((char*)Kh + off + 4) = h1;
            round4h(vr[i], h0, h1);
            *(uint32_t*)((char*)Vh + off)     = h0;
            *(uint32_t*)((char*)Vh + off + 4) = h1;
        }
        __syncthreads();

        // ---- issue next tile's global loads (hidden by compute) ----
        if (jt + 1 < ntiles) {
            const float* kp = Kp + ((size_t)((jt + 1) * 64 + srow) << 7) + scb;
            const float* vp = Vp + ((size_t)((jt + 1) * 64 + srow) << 7) + scb;
            #pragma unroll
            for (int i = 0; i < 8; ++i) {
                kr[i] = *(const float4*)(kp + (i << 2));
                vr[i] = *(const float4*)(vp + (i << 2));
            }
        }

        // ---- S = (Qh+Ql) K^T, 2 fp16 terms ----
        float s[8][4];
        #pragma unroll
        for (int t8 = 0; t8 < 8; ++t8)
            #pragma unroll
            for (int e = 0; e < 4; ++e) s[t8][e] = 0.f;

        #pragma unroll
        for (int ks = 0; ks < 8; ++ks) {
            uint32_t aoff = (uint32_t)((wid * 16 + r16) * FSP + ks * 16 + (hsel << 3)) << 1;
            uint32_t ah0, ah1, ah2, ah3, al0, al1, al2, al3;
            ldm_x4(ah0, ah1, ah2, ah3, uQh + aoff);
            ldm_x4(al0, al1, al2, al3, uQl + aoff);
            #pragma unroll
            for (int nt = 0; nt < 4; ++nt) {
                uint32_t koff = (uint32_t)((nt * 16 + r16) * FSP + ks * 16 + (hsel << 3)) << 1;
                uint32_t kh0, kh1, kh2, kh3;
                ldm_x4(kh0, kh1, kh2, kh3, uKh + koff);
                mma16816h(s[2*nt],   ah0, ah1, ah2, ah3, kh0, kh2);
                mma16816h(s[2*nt+1], ah0, ah1, ah2, ah3, kh1, kh3);
                mma16816h(s[2*nt],   al0, al1, al2, al3, kh0, kh2);
                mma16816h(s[2*nt+1], al0, al1, al2, al3, kh1, kh3);
            }
        }

        // ---- scale + causal mask ----
        int kvb = jt * 64;
        int qr0 = qbase + g;
        bool needmask = (kvb + 63 > qbase);
        #pragma unroll
        for (int t8 = 0; t8 < 8; ++t8) {
            #pragma unroll
            for (int e = 0; e < 4; ++e) {
                float val = s[t8][e] * alpha;
                if (needmask) {
                    int col = kvb + t8 * 8 + qd * 2 + (e & 1);
                    int row = (e < 2) ? qr0 : qr0 + 8;
                    if (col > row) val = -1e30f;
                }
                s[t8][e] = val;
            }
        }

        // ---- online softmax (quad reductions) ----
        float tm0 = -1e30f, tm1 = -1e30f;
        #pragma unroll
        for (int t8 = 0; t8 < 8; ++t8) {
            tm0 = fmaxf(tm0, fmaxf(s[t8][0], s[t8][1]));
            tm1 = fmaxf(tm1, fmaxf(s[t8][2], s[t8][3]));
        }
        tm0 = fmaxf(tm0, __shfl_xor_sync(0xffffffffu, tm0, 1));
        tm0 = fmaxf(tm0, __shfl_xor_sync(0xffffffffu, tm0, 2));
        tm1 = fmaxf(tm1, __shfl_xor_sync(0xffffffffu, tm1, 1));
        tm1 = fmaxf(tm1, __shfl_xor_sync(0xffffffffu, tm1, 2));
        float nm0 = fmaxf(m0, tm0), nm1 = fmaxf(m1, tm1);
        float c0 = ex2(m0 - nm0), c1 = ex2(m1 - nm1);
        m0 = nm0; m1 = nm1;

        float ps0 = 0.f, ps1 = 0.f;
        #pragma unroll
        for (int t8 = 0; t8 < 8; ++t8) {
            s[t8][0] = ex2(s[t8][0] - nm0);
            s[t8][1] = ex2(s[t8][1] - nm0);
            s[t8][2] = ex2(s[t8][2] - nm1);
            s[t8][3] = ex2(s[t8][3] - nm1);
            ps0 += s[t8][0] + s[t8][1];
            ps1 += s[t8][2] + s[t8][3];
        }
        ps0 += __shfl_xor_sync(0xffffffffu, ps0, 1);
        ps0 += __shfl_xor_sync(0xffffffffu, ps0, 2);
        ps1 += __shfl_xor_sync(0xffffffffu, ps1, 1);
        ps1 += __shfl_xor_sync(0xffffffffu, ps1, 2);
        l0 = l0 * c0 + ps0;
        l1 = l1 * c1 + ps1;

        #pragma unroll
        for (int dt = 0; dt < 16; ++dt) {
            o[dt][0] *= c0; o[dt][1] *= c0;
            o[dt][2] *= c1; o[dt][3] *= c1;
        }

        // ---- O += P V (1 fp16 term) ----
        #pragma unroll
        for (int j = 0; j < 4; ++j) {
            uint32_t ph0 = pack_h(s[2*j][0],   s[2*j][1]);
            uint32_t ph1 = pack_h(s[2*j][2],   s[2*j][3]);
            uint32_t ph2 = pack_h(s[2*j+1][0], s[2*j+1][1]);
            uint32_t ph3 = pack_h(s[2*j+1][2], s[2*j+1][3]);
            #pragma unroll
            for (int dt = 0; dt < 8; ++dt) {
                uint32_t voff = (uint32_t)((j * 16 + r16) * FSP + dt * 16 + (hsel << 3)) << 1;
                uint32_t vh0, vh1, vh2, vh3;
                ldm_x4_trans(vh0, vh1, vh2, vh3, uVh + voff);
                mma16816h(o[2*dt],   ph0, ph1, ph2, ph3, vh0, vh1);
                mma16816h(o[2*dt+1], ph0, ph1, ph2, ph3, vh2, vh3);
            }
        }
    }

    // ---- finalize ----
    float li0 = 1.f / l0, li1 = 1.f / l1;
    int t0 = qbase + g;
    float* dst0 = ctx + (size_t)(b * Tt + t0) * HIDD + h * HD;
    float* dst1 = ctx + (size_t)(b * Tt + t0 + 8) * HIDD + h * HD;
    #pragma unroll
    for (int dt = 0; dt < 16; ++dt) {
        int col = dt * 8 + qd * 2;
        float2 w0 = make_float2(o[dt][0] * li0, o[dt][1] * li0);
        float2 w1 = make_float2(o[dt][2] * li1, o[dt][3] * li1);
        *(float2*)(dst0 + col) = w0;
        *(float2*)(dst1 + col) = w1;
    }
}

// ---------------- launch ----------------
extern "C" void kernel_launch(void* const* d_in, const int* in_sizes, int n_in,
                              void* d_out, int out_size)
{
    const float* hs   = (const float*)d_in[0];
    const float* cosp = (const float*)d_in[2];
    const float* sinp = (const float*)d_in[3];
    const float* Wq   = (const float*)d_in[4];
    const float* Wk   = (const float*)d_in[5];
    const float* Wv   = (const float*)d_in[6];
    const float* Wo   = (const float*)d_in[7];
    float* out = (float*)d_out;

    float *pQ, *pK, *pV, *pC;
    cudaGetSymbolAddress((void**)&pQ, g_Q);
    cudaGetSymbolAddress((void**)&pK, g_K);
    cudaGetSymbolAddress((void**)&pV, g_V);
    cudaGetSymbolAddress((void**)&pC, g_ctx);

    // Fused QKV projection (fp16 2-term)
    qkv_gemm_kernel<<<dim3(24, 32), 256>>>(hs, Wq, Wk, Wv, pQ, pK, pV);

    // RoPE on Q and K
    int totQ = Bb * NH  * Tt * 64;
    int totK = Bb * KVH * Tt * 64;
    rope_kernel<<<totQ / 256, 256>>>(pQ, cosp, sinp, totQ);
    rope_kernel<<<totK / 256, 256>>>(pK, cosp, sinp, totK);

    // Flash attention (fp16 2-term S, 1-term PV)
    size_t fsh = (size_t)(2 * 128 * FSP + 2 * 64 * FSP) * sizeof(uint16_t); // 104448
    cudaFuncSetAttribute(flash_mma_kernel, cudaFuncAttributeMaxDynamicSharedMemorySize, (int)fsh);
    flash_mma_kernel<<<dim3(Tt/128, Bb*NH), 256, fsh>>>(pQ, pK, pV, pC);

    // Output projection (fp16 2-term) -> d_out
    tc_gemm_kernel<<<dim3(16, 32), 256>>>(pC, Wo, out, HIDD, HIDD, 0, 0);
}